// round 1
// baseline (speedup 1.0000x reference)
#include <cuda_runtime.h>
#include <math.h>

#define LSEQ 2048
#define BATCH 8
#define NH 4
#define HDIM 64
#define DM 256
#define DOUT 1024
#define NTOK (BATCH*LSEQ)   // 16384

// Scratch (device globals -- no runtime allocation allowed)
__device__ float g_Q[(size_t)BATCH*NH*LSEQ*HDIM];   // [b,h,l,hd]
__device__ float g_K[(size_t)BATCH*NH*LSEQ*HDIM];
__device__ float g_V[(size_t)BATCH*NH*LSEQ*HDIM];
__device__ float g_CTX[(size_t)NTOK*DM];            // [b,l, h*64+j]

// ---------------------------------------------------------------------------
// Tiled fp32 GEMM: C[M,N] = A[M,256] @ W[256,N] + bias
// 64x64 tile, BK=16, 256 threads, 4x4 microtile, float4 SMEM loads.
// MODE 1: QKV projection -> writes g_Q/g_K/g_V in [b,h,l,hd] layout (which selects)
// MODE 0: output projection -> reads g_CTX, writes C plain row-major
// ---------------------------------------------------------------------------
template<int N, int MODE>
__global__ __launch_bounds__(256)
void gemm64(const float* __restrict__ A, const float* __restrict__ W,
            const float* __restrict__ bias, float* __restrict__ C, int which)
{
    __shared__ float As[16][68];   // A staged transposed: As[k][m], pad 68
    __shared__ float Bs[16][64];   // W staged natural:   Bs[k][n]

    const int tid = threadIdx.x;
    const int ty = tid >> 4, tx = tid & 15;
    const int row0 = blockIdx.x << 6;
    const int col0 = blockIdx.y << 6;

    const float* Asrc = (MODE == 0) ? g_CTX : A;

    const int am = tid >> 2;            // 0..63
    const int ak = (tid & 3) << 2;      // 0,4,8,12
    const int bk = tid >> 4;            // 0..15
    const int bn = (tid & 15) << 2;     // 0..60

    const float* aptr = Asrc + (size_t)(row0 + am) * DM + ak;
    const float* wptr = W + (size_t)bk * N + col0 + bn;

    float acc[4][4];
    #pragma unroll
    for (int i = 0; i < 4; i++)
        #pragma unroll
        for (int j = 0; j < 4; j++) acc[i][j] = 0.f;

    #pragma unroll 1
    for (int k0 = 0; k0 < DM; k0 += 16) {
        float4 av = *(const float4*)aptr;  aptr += 16;
        float4 wv = *(const float4*)wptr;  wptr += (size_t)16 * N;

        As[ak+0][am] = av.x;
        As[ak+1][am] = av.y;
        As[ak+2][am] = av.z;
        As[ak+3][am] = av.w;
        *(float4*)&Bs[bk][bn] = wv;
        __syncthreads();

        #pragma unroll
        for (int kk = 0; kk < 16; kk++) {
            float4 a4 = *(const float4*)&As[kk][ty << 2];
            float4 b4 = *(const float4*)&Bs[kk][tx << 2];
            float aa[4] = {a4.x, a4.y, a4.z, a4.w};
            float bb[4] = {b4.x, b4.y, b4.z, b4.w};
            #pragma unroll
            for (int i = 0; i < 4; i++)
                #pragma unroll
                for (int j = 0; j < 4; j++)
                    acc[i][j] = fmaf(aa[i], bb[j], acc[i][j]);
        }
        __syncthreads();
    }

    const int c0 = col0 + (tx << 2);
    #pragma unroll
    for (int i = 0; i < 4; i++) {
        int r = row0 + (ty << 2) + i;
        float4 o;
        o.x = acc[i][0] + bias[c0 + 0];
        o.y = acc[i][1] + bias[c0 + 1];
        o.z = acc[i][2] + bias[c0 + 2];
        o.w = acc[i][3] + bias[c0 + 3];
        if (MODE == 0) {
            *(float4*)&C[(size_t)r * N + c0] = o;
        } else {
            int b = r >> 11;            // r / 2048
            int l = r & 2047;
            int h = col0 >> 6;          // whole tile is inside one head (N tiles align)
            int j2 = c0 & 63;           // = 4*tx
            float* dst = (which == 0) ? g_Q : (which == 1) ? g_K : g_V;
            *(float4*)&dst[(((size_t)(b * NH + h) * LSEQ) + l) * HDIM + j2] = o;
        }
    }
}

// ---------------------------------------------------------------------------
// Flash attention, fp32. One block = one (b,h) x 64-query tile. 256 threads.
// SMEM: Qt[64][68] (transposed, pre-scaled), KP[64][68] (Kt then P), Vs[64][64]
// ---------------------------------------------------------------------------
#define ATTN_SMEM ((2*64*68 + 64*64) * 4)   // 51200 bytes

__global__ __launch_bounds__(256)
void attn_kernel()
{
    extern __shared__ float sm[];
    float* Qt = sm;                 // [d][q]  pitch 68
    float* KP = sm + 64*68;         // Kt: [d][k] pitch 68 ; later P: [q][k] pitch 68
    float* Vs = sm + 2*64*68;       // [k][d]  pitch 64

    const int tid = threadIdx.x;
    const int ty = tid >> 4, tx = tid & 15;
    const int q0 = blockIdx.x << 6;
    const int bh = blockIdx.y;

    const float* Qg = g_Q + (size_t)bh * LSEQ * HDIM;
    const float* Kg = g_K + (size_t)bh * LSEQ * HDIM;
    const float* Vg = g_V + (size_t)bh * LSEQ * HDIM;

    const float scale = 0.0625f;    // 1/sqrt(256)

    // Load Q tile, transposed + pre-scaled: Qt[d][q]
    #pragma unroll
    for (int i = 0; i < 4; i++) {
        int e = tid + i * 256;      // 0..1023
        int l = e >> 4;             // 0..63
        int d4 = (e & 15) << 2;     // 0..60
        float4 v = *(const float4*)(Qg + (size_t)(q0 + l) * HDIM + d4);
        Qt[(d4+0)*68 + l] = v.x * scale;
        Qt[(d4+1)*68 + l] = v.y * scale;
        Qt[(d4+2)*68 + l] = v.z * scale;
        Qt[(d4+3)*68 + l] = v.w * scale;
    }

    float acc[4][4];
    float mi[4], li[4];
    #pragma unroll
    for (int i = 0; i < 4; i++) {
        mi[i] = -1e30f; li[i] = 0.f;
        #pragma unroll
        for (int j = 0; j < 4; j++) acc[i][j] = 0.f;
    }

    #pragma unroll 1
    for (int kt = 0; kt < LSEQ / 64; kt++) {
        const int k0 = kt << 6;

        // Stage K (transposed) and V (natural)
        #pragma unroll
        for (int i = 0; i < 4; i++) {
            int e = tid + i * 256;
            int l = e >> 4;
            int d4 = (e & 15) << 2;
            float4 kv = *(const float4*)(Kg + (size_t)(k0 + l) * HDIM + d4);
            KP[(d4+0)*68 + l] = kv.x;
            KP[(d4+1)*68 + l] = kv.y;
            KP[(d4+2)*68 + l] = kv.z;
            KP[(d4+3)*68 + l] = kv.w;
            float4 vv = *(const float4*)(Vg + (size_t)(k0 + l) * HDIM + d4);
            *(float4*)&Vs[l * 64 + d4] = vv;
        }
        __syncthreads();

        // S = Q K^T  (per-thread 4x4 of the 64x64 tile)
        float s[4][4];
        #pragma unroll
        for (int i = 0; i < 4; i++)
            #pragma unroll
            for (int j = 0; j < 4; j++) s[i][j] = 0.f;

        #pragma unroll 8
        for (int d = 0; d < 64; d++) {
            float4 qa = *(const float4*)&Qt[d*68 + (ty << 2)];
            float4 kb = *(const float4*)&KP[d*68 + (tx << 2)];
            float qq[4] = {qa.x, qa.y, qa.z, qa.w};
            float kk[4] = {kb.x, kb.y, kb.z, kb.w};
            #pragma unroll
            for (int i = 0; i < 4; i++)
                #pragma unroll
                for (int j = 0; j < 4; j++)
                    s[i][j] = fmaf(qq[i], kk[j], s[i][j]);
        }
        __syncthreads();   // all Kt reads done; KP may be overwritten with P

        // Online softmax update (row = 16 lanes of a half-warp)
        #pragma unroll
        for (int i = 0; i < 4; i++) {
            float rm = fmaxf(fmaxf(s[i][0], s[i][1]), fmaxf(s[i][2], s[i][3]));
            #pragma unroll
            for (int off = 8; off >= 1; off >>= 1)
                rm = fmaxf(rm, __shfl_xor_sync(0xffffffffu, rm, off));
            float mnew = fmaxf(mi[i], rm);
            float corr = __expf(mi[i] - mnew);
            mi[i] = mnew;
            float rs = 0.f;
            #pragma unroll
            for (int j = 0; j < 4; j++) {
                s[i][j] = __expf(s[i][j] - mnew);
                rs += s[i][j];
            }
            #pragma unroll
            for (int off = 8; off >= 1; off >>= 1)
                rs += __shfl_xor_sync(0xffffffffu, rs, off);
            li[i] = li[i] * corr + rs;
            #pragma unroll
            for (int j = 0; j < 4; j++) acc[i][j] *= corr;
        }

        // Store P natural [q][k] (consecutive-lane float4 stores, conflict-free)
        #pragma unroll
        for (int i = 0; i < 4; i++) {
            float4 pv = make_float4(s[i][0], s[i][1], s[i][2], s[i][3]);
            *(float4*)&KP[((ty << 2) + i) * 68 + (tx << 2)] = pv;
        }
        __syncthreads();

        // acc += P @ V   (k unrolled by 4: 8 LDS.128 per 64 FMA)
        #pragma unroll 4
        for (int k = 0; k < 64; k += 4) {
            float4 p[4];
            #pragma unroll
            for (int i = 0; i < 4; i++)
                p[i] = *(const float4*)&KP[((ty << 2) + i) * 68 + k];
            float4 v0 = *(const float4*)&Vs[(k+0) * 64 + (tx << 2)];
            float4 v1 = *(const float4*)&Vs[(k+1) * 64 + (tx << 2)];
            float4 v2 = *(const float4*)&Vs[(k+2) * 64 + (tx << 2)];
            float4 v3 = *(const float4*)&Vs[(k+3) * 64 + (tx << 2)];
            float vm[4][4] = {{v0.x,v0.y,v0.z,v0.w},
                              {v1.x,v1.y,v1.z,v1.w},
                              {v2.x,v2.y,v2.z,v2.w},
                              {v3.x,v3.y,v3.z,v3.w}};
            #pragma unroll
            for (int i = 0; i < 4; i++) {
                float pp[4] = {p[i].x, p[i].y, p[i].z, p[i].w};
                #pragma unroll
                for (int j = 0; j < 4; j++) {
                    float a = acc[i][j];
                    a = fmaf(pp[0], vm[0][j], a);
                    a = fmaf(pp[1], vm[1][j], a);
                    a = fmaf(pp[2], vm[2][j], a);
                    a = fmaf(pp[3], vm[3][j], a);
                    acc[i][j] = a;
                }
            }
        }
        __syncthreads();   // protect KP/Vs before next tile's stage
    }

    // Epilogue: normalize and write ctx in [b, l, h*64+j] layout for the out-proj GEMM
    const int b = bh >> 2;
    const int h = bh & 3;
    #pragma unroll
    for (int i = 0; i < 4; i++) {
        float inv = 1.0f / li[i];
        int r = q0 + (ty << 2) + i;
        float4 o = make_float4(acc[i][0]*inv, acc[i][1]*inv, acc[i][2]*inv, acc[i][3]*inv);
        *(float4*)&g_CTX[((size_t)(b * LSEQ + r)) * DM + h * HDIM + (tx << 2)] = o;
    }
}

// ---------------------------------------------------------------------------
extern "C" void kernel_launch(void* const* d_in, const int* in_sizes, int n_in,
                              void* d_out, int out_size)
{
    const float* x  = (const float*)d_in[0];
    const float* Wq = (const float*)d_in[1];
    const float* bq = (const float*)d_in[2];
    const float* Wk = (const float*)d_in[3];
    const float* bk = (const float*)d_in[4];
    const float* Wv = (const float*)d_in[5];
    const float* bv = (const float*)d_in[6];
    const float* Wo = (const float*)d_in[7];
    const float* bo = (const float*)d_in[8];
    float* out = (float*)d_out;

    // QKV projections -> g_Q/g_K/g_V in [b,h,l,hd]
    dim3 gp(NTOK / 64, DM / 64);     // (256, 4)
    gemm64<DM, 1><<<gp, 256>>>(x, Wq, bq, nullptr, 0);
    gemm64<DM, 1><<<gp, 256>>>(x, Wk, bk, nullptr, 1);
    gemm64<DM, 1><<<gp, 256>>>(x, Wv, bv, nullptr, 2);

    // Flash attention -> g_CTX
    cudaFuncSetAttribute(attn_kernel, cudaFuncAttributeMaxDynamicSharedMemorySize, ATTN_SMEM);
    attn_kernel<<<dim3(LSEQ / 64, BATCH * NH), 256, ATTN_SMEM>>>();

    // Output projection -> d_out
    dim3 go(NTOK / 64, DOUT / 64);   // (256, 16)
    gemm64<DOUT, 0><<<go, 256>>>(nullptr, Wo, bo, out, 0);
}

// round 2
// speedup vs baseline: 1.1375x; 1.1375x over previous
#include <cuda_runtime.h>
#include <stdint.h>

typedef unsigned long long u64;

#define LSEQ 2048
#define BATCH 8
#define NH 4
#define HDIM 64
#define DM 256
#define DOUT 1024
#define NTOK (BATCH*LSEQ)   // 16384
#define QP 132              // SMEM pitch (floats) for transposed tiles

// Scratch (device globals -- no runtime allocation allowed)
__device__ float g_Q[(size_t)BATCH*NH*LSEQ*HDIM];   // [b,h,l,hd]
__device__ float g_K[(size_t)BATCH*NH*LSEQ*HDIM];
__device__ float g_V[(size_t)BATCH*NH*LSEQ*HDIM];
__device__ float g_CTX[(size_t)NTOK*DM];            // [b,l, h*64+j]

// ---------------- packed f32x2 helpers ----------------
__device__ __forceinline__ u64 pack2(float lo, float hi){
    u64 r; asm("mov.b64 %0,{%1,%2};":"=l"(r):"f"(lo),"f"(hi)); return r; }
__device__ __forceinline__ void unpack2(u64 v, float &lo, float &hi){
    asm("mov.b64 {%0,%1},%2;":"=f"(lo),"=f"(hi):"l"(v)); }
__device__ __forceinline__ u64 dup2(float x){ return pack2(x,x); }
__device__ __forceinline__ void fma2(u64 &d, u64 a, u64 b){
    asm("fma.rn.f32x2 %0,%1,%2,%0;":"+l"(d):"l"(a),"l"(b)); }
__device__ __forceinline__ void mul2(u64 &d, u64 a){
    asm("mul.rn.f32x2 %0,%0,%1;":"+l"(d):"l"(a)); }
__device__ __forceinline__ void lds2x64(u64 &x, u64 &y, uint32_t a){
    asm volatile("ld.shared.v2.b64 {%0,%1},[%2];":"=l"(x),"=l"(y):"r"(a)); }
__device__ __forceinline__ void sts64(uint32_t a, u64 v){
    asm volatile("st.shared.b64 [%0],%1;"::"r"(a),"l"(v):"memory"); }

// ===========================================================================
// GEMM: C[M,256]@W[256,N]+b. 128x64 tile, 256 thr, 8x4 microtile, f32x2.
// ===========================================================================
__device__ __forceinline__ void gemm_core(
    const float* __restrict__ A, const float* __restrict__ W, int wstride,
    float* As /*16*QP*/, float* Ws /*16*64*/, int row0, int col0, u64 (&acc)[4][4])
{
    const int tid = threadIdx.x, ty = tid>>4, tx = tid&15;
    const int m0 = tid>>2;               // 0..63
    const int k4 = (tid&3)<<2;           // 0,4,8,12

    const float* ap0 = A + (size_t)(row0+m0)*DM + k4;
    const float* ap1 = ap0 + (size_t)64*DM;
    const int wk = tid>>4, wn = (tid&15)<<2;
    const float* wp = W + (size_t)wk*wstride + col0 + wn;

    uint32_t as_b = (uint32_t)__cvta_generic_to_shared(As);

    float4 ar0 = *(const float4*)ap0;
    float4 ar1 = *(const float4*)ap1;
    float4 wr  = *(const float4*)wp;

    #pragma unroll 1
    for (int k0 = 0; k0 < DM; k0 += 16) {
        As[(k4+0)*QP + m0]      = ar0.x;
        As[(k4+1)*QP + m0]      = ar0.y;
        As[(k4+2)*QP + m0]      = ar0.z;
        As[(k4+3)*QP + m0]      = ar0.w;
        As[(k4+0)*QP + m0 + 64] = ar1.x;
        As[(k4+1)*QP + m0 + 64] = ar1.y;
        As[(k4+2)*QP + m0 + 64] = ar1.z;
        As[(k4+3)*QP + m0 + 64] = ar1.w;
        *(float4*)&Ws[wk*64 + wn] = wr;
        __syncthreads();

        if (k0 + 16 < DM) {   // prefetch next slab
            ar0 = *(const float4*)(ap0 + k0 + 16);
            ar1 = *(const float4*)(ap1 + k0 + 16);
            wr  = *(const float4*)(wp + (size_t)(k0+16)*wstride);
        }

        uint32_t qa = as_b + ty*32;
        #pragma unroll
        for (int kk = 0; kk < 16; kk++) {
            u64 a0,a1,a2,a3;
            lds2x64(a0,a1, qa + kk*(QP*4));
            lds2x64(a2,a3, qa + kk*(QP*4) + 16);
            float4 b4 = *(const float4*)&Ws[kk*64 + (tx<<2)];
            u64 b0=dup2(b4.x), b1=dup2(b4.y), b2=dup2(b4.z), b3=dup2(b4.w);
            fma2(acc[0][0],a0,b0); fma2(acc[0][1],a0,b1); fma2(acc[0][2],a0,b2); fma2(acc[0][3],a0,b3);
            fma2(acc[1][0],a1,b0); fma2(acc[1][1],a1,b1); fma2(acc[1][2],a1,b2); fma2(acc[1][3],a1,b3);
            fma2(acc[2][0],a2,b0); fma2(acc[2][1],a2,b1); fma2(acc[2][2],a2,b2); fma2(acc[2][3],a2,b3);
            fma2(acc[3][0],a3,b0); fma2(acc[3][1],a3,b1); fma2(acc[3][2],a3,b2); fma2(acc[3][3],a3,b3);
        }
        __syncthreads();
    }
}

__global__ __launch_bounds__(256)
void gemm_qkv(const float* __restrict__ x,
              const float* __restrict__ Wq, const float* __restrict__ bq,
              const float* __restrict__ Wk, const float* __restrict__ bk,
              const float* __restrict__ Wv, const float* __restrict__ bv)
{
    __shared__ __align__(16) float As[16*QP];
    __shared__ __align__(16) float Ws[16*64];
    const int tid = threadIdx.x, ty = tid>>4, tx = tid&15;
    const int row0 = blockIdx.x<<7;
    const int yy = blockIdx.y, mat = yy>>2, col0 = (yy&3)<<6;
    const float* W    = (mat==0)?Wq:(mat==1)?Wk:Wv;
    const float* bias = (mat==0)?bq:(mat==1)?bk:bv;
    float* dst        = (mat==0)?g_Q:(mat==1)?g_K:g_V;

    u64 acc[4][4];
    #pragma unroll
    for (int i=0;i<4;i++){ acc[i][0]=0; acc[i][1]=0; acc[i][2]=0; acc[i][3]=0; }

    gemm_core(x, W, DM, As, Ws, row0, col0, acc);

    const int b = row0>>11;
    const int lbase = (row0 & 2047) + (ty<<3);
    float* dbase = dst + ((size_t)(b*NH + (col0>>6))*LSEQ)*HDIM + (tx<<2);
    float4 bb = *(const float4*)&bias[col0 + (tx<<2)];
    #pragma unroll
    for (int ip=0; ip<4; ip++) {
        float lo[4], hi[4];
        unpack2(acc[ip][0],lo[0],hi[0]); unpack2(acc[ip][1],lo[1],hi[1]);
        unpack2(acc[ip][2],lo[2],hi[2]); unpack2(acc[ip][3],lo[3],hi[3]);
        int l = lbase + (ip<<1);
        float4 o0 = make_float4(lo[0]+bb.x, lo[1]+bb.y, lo[2]+bb.z, lo[3]+bb.w);
        float4 o1 = make_float4(hi[0]+bb.x, hi[1]+bb.y, hi[2]+bb.z, hi[3]+bb.w);
        *(float4*)&dbase[(size_t)l*HDIM]     = o0;
        *(float4*)&dbase[(size_t)(l+1)*HDIM] = o1;
    }
}

__global__ __launch_bounds__(256)
void gemm_out(const float* __restrict__ Wo, const float* __restrict__ bo,
              float* __restrict__ C)
{
    __shared__ __align__(16) float As[16*QP];
    __shared__ __align__(16) float Ws[16*64];
    const int tid = threadIdx.x, ty = tid>>4, tx = tid&15;
    const int row0 = blockIdx.x<<7;
    const int col0 = blockIdx.y<<6;

    u64 acc[4][4];
    #pragma unroll
    for (int i=0;i<4;i++){ acc[i][0]=0; acc[i][1]=0; acc[i][2]=0; acc[i][3]=0; }

    gemm_core(g_CTX, Wo, DOUT, As, Ws, row0, col0, acc);

    float4 bb = *(const float4*)&bo[col0 + (tx<<2)];
    const int rbase = row0 + (ty<<3);
    #pragma unroll
    for (int ip=0; ip<4; ip++) {
        float lo[4], hi[4];
        unpack2(acc[ip][0],lo[0],hi[0]); unpack2(acc[ip][1],lo[1],hi[1]);
        unpack2(acc[ip][2],lo[2],hi[2]); unpack2(acc[ip][3],lo[3],hi[3]);
        int r = rbase + (ip<<1);
        float4 o0 = make_float4(lo[0]+bb.x, lo[1]+bb.y, lo[2]+bb.z, lo[3]+bb.w);
        float4 o1 = make_float4(hi[0]+bb.x, hi[1]+bb.y, hi[2]+bb.z, hi[3]+bb.w);
        *(float4*)&C[(size_t)r*DOUT + col0 + (tx<<2)]     = o0;
        *(float4*)&C[(size_t)(r+1)*DOUT + col0 + (tx<<2)] = o1;
    }
}

// ===========================================================================
// Flash attention fp32 + f32x2. Block = (b,h) x 128-query tile, 256 threads.
// Microtile 8(q) x 4(k). SMEM: Qt[d][q], KP = Kt[d][k] then Pt[k][q], Vs[k][d].
// ===========================================================================
#define ATTN_SMEM ((64*QP*2 + 64*64)*4)   // 83968 bytes -> 2 CTAs/SM

__global__ __launch_bounds__(256,2)
void attn_kernel()
{
    extern __shared__ __align__(16) float sm[];
    float* Qt = sm;               // [64][QP]  (d, q)  pre-scaled
    float* KP = sm + 64*QP;       // Kt: [64][QP] (d,k) ; later Pt: [64][QP] (k,q)
    float* Vs = sm + 2*64*QP;     // [64][64]  (k, d)

    uint32_t qt_b = (uint32_t)__cvta_generic_to_shared(Qt);
    uint32_t kp_b = (uint32_t)__cvta_generic_to_shared(KP);

    const int tid = threadIdx.x, ty = tid>>4, tx = tid&15;
    const int q0 = blockIdx.x<<7;
    const int bh = blockIdx.y;

    const float* Qg = g_Q + (size_t)bh*LSEQ*HDIM;
    const float* Kg = g_K + (size_t)bh*LSEQ*HDIM;
    const float* Vg = g_V + (size_t)bh*LSEQ*HDIM;
    const float scale = 0.0625f;   // 1/sqrt(256)

    // Stage Q tile transposed + pre-scaled
    #pragma unroll
    for (int i=0;i<8;i++){
        int e = tid + (i<<8);
        int q = e>>4, d4 = (e&15)<<2;
        float4 v = *(const float4*)(Qg + (size_t)(q0+q)*HDIM + d4);
        Qt[(d4+0)*QP+q] = v.x*scale;
        Qt[(d4+1)*QP+q] = v.y*scale;
        Qt[(d4+2)*QP+q] = v.z*scale;
        Qt[(d4+3)*QP+q] = v.w*scale;
    }

    u64 acc[4][4];
    float mi[8], li[8];
    #pragma unroll
    for (int i=0;i<4;i++){ acc[i][0]=0; acc[i][1]=0; acc[i][2]=0; acc[i][3]=0; }
    #pragma unroll
    for (int i=0;i<8;i++){ mi[i] = -1e30f; li[i] = 0.f; }

    #pragma unroll 1
    for (int kt = 0; kt < LSEQ/64; kt++) {
        const int k0 = kt<<6;

        // Stage K (transposed) + V (natural)
        #pragma unroll
        for (int i=0;i<4;i++){
            int e = tid + (i<<8);
            int k = e>>4, d4 = (e&15)<<2;
            float4 kv = *(const float4*)(Kg + (size_t)(k0+k)*HDIM + d4);
            KP[(d4+0)*QP+k] = kv.x;
            KP[(d4+1)*QP+k] = kv.y;
            KP[(d4+2)*QP+k] = kv.z;
            KP[(d4+3)*QP+k] = kv.w;
            float4 vv = *(const float4*)(Vg + (size_t)(k0+k)*HDIM + d4);
            *(float4*)&Vs[(k<<6)+d4] = vv;
        }
        __syncthreads();

        // S = Q K^T : s2[ip][j] packs q rows (2ip, 2ip+1), col 4tx+j
        u64 s2[4][4];
        #pragma unroll
        for (int i=0;i<4;i++){ s2[i][0]=0; s2[i][1]=0; s2[i][2]=0; s2[i][3]=0; }
        {
            uint32_t qa = qt_b + ty*32;
            #pragma unroll 8
            for (int d=0; d<64; d++){
                u64 a0,a1,a2,a3;
                lds2x64(a0,a1, qa + d*(QP*4));
                lds2x64(a2,a3, qa + d*(QP*4) + 16);
                float4 kb = *(const float4*)&KP[d*QP + (tx<<2)];
                u64 b0=dup2(kb.x), b1=dup2(kb.y), b2=dup2(kb.z), b3=dup2(kb.w);
                fma2(s2[0][0],a0,b0); fma2(s2[0][1],a0,b1); fma2(s2[0][2],a0,b2); fma2(s2[0][3],a0,b3);
                fma2(s2[1][0],a1,b0); fma2(s2[1][1],a1,b1); fma2(s2[1][2],a1,b2); fma2(s2[1][3],a1,b3);
                fma2(s2[2][0],a2,b0); fma2(s2[2][1],a2,b1); fma2(s2[2][2],a2,b2); fma2(s2[2][3],a2,b3);
                fma2(s2[3][0],a3,b0); fma2(s2[3][1],a3,b1); fma2(s2[3][2],a3,b2); fma2(s2[3][3],a3,b3);
            }
        }
        __syncthreads();   // Kt reads done; KP becomes Pt

        // Online softmax (two rows per pair), store Pt transposed [k][q]
        #pragma unroll
        for (int ip=0; ip<4; ip++){
            float l0[4], l1[4];
            unpack2(s2[ip][0],l0[0],l1[0]); unpack2(s2[ip][1],l0[1],l1[1]);
            unpack2(s2[ip][2],l0[2],l1[2]); unpack2(s2[ip][3],l0[3],l1[3]);
            float rm0 = fmaxf(fmaxf(l0[0],l0[1]), fmaxf(l0[2],l0[3]));
            float rm1 = fmaxf(fmaxf(l1[0],l1[1]), fmaxf(l1[2],l1[3]));
            #pragma unroll
            for (int off=8; off>=1; off>>=1){
                rm0 = fmaxf(rm0, __shfl_xor_sync(0xffffffffu, rm0, off));
                rm1 = fmaxf(rm1, __shfl_xor_sync(0xffffffffu, rm1, off));
            }
            const int r0 = ip<<1, r1 = (ip<<1)+1;
            float mn0 = fmaxf(mi[r0], rm0), mn1 = fmaxf(mi[r1], rm1);
            float c0 = __expf(mi[r0]-mn0),  c1 = __expf(mi[r1]-mn1);
            mi[r0]=mn0; mi[r1]=mn1;
            float rs0=0.f, rs1=0.f;
            #pragma unroll
            for (int j=0;j<4;j++){
                l0[j] = __expf(l0[j]-mn0); rs0 += l0[j];
                l1[j] = __expf(l1[j]-mn1); rs1 += l1[j];
            }
            #pragma unroll
            for (int off=8; off>=1; off>>=1){
                rs0 += __shfl_xor_sync(0xffffffffu, rs0, off);
                rs1 += __shfl_xor_sync(0xffffffffu, rs1, off);
            }
            li[r0] = li[r0]*c0 + rs0;
            li[r1] = li[r1]*c1 + rs1;
            u64 c2 = pack2(c0, c1);
            mul2(acc[ip][0],c2); mul2(acc[ip][1],c2); mul2(acc[ip][2],c2); mul2(acc[ip][3],c2);
            // Pt[k=4tx+j][q = 8ty+2ip (+1)]
            uint32_t pa = kp_b + (((tx<<2))*QP + (ty<<3) + (ip<<1))*4;
            sts64(pa,           pack2(l0[0],l1[0]));
            sts64(pa + QP*4,    pack2(l0[1],l1[1]));
            sts64(pa + QP*8,    pack2(l0[2],l1[2]));
            sts64(pa + QP*12,   pack2(l0[3],l1[3]));
        }
        __syncthreads();

        // acc += P @ V
        {
            uint32_t pa2 = kp_b + ty*32;
            #pragma unroll 8
            for (int k=0; k<64; k++){
                u64 p0,p1,p2,p3;
                lds2x64(p0,p1, pa2 + k*(QP*4));
                lds2x64(p2,p3, pa2 + k*(QP*4) + 16);
                float4 vv = *(const float4*)&Vs[(k<<6) + (tx<<2)];
                u64 v0=dup2(vv.x), v1=dup2(vv.y), v2=dup2(vv.z), v3=dup2(vv.w);
                fma2(acc[0][0],p0,v0); fma2(acc[0][1],p0,v1); fma2(acc[0][2],p0,v2); fma2(acc[0][3],p0,v3);
                fma2(acc[1][0],p1,v0); fma2(acc[1][1],p1,v1); fma2(acc[1][2],p1,v2); fma2(acc[1][3],p1,v3);
                fma2(acc[2][0],p2,v0); fma2(acc[2][1],p2,v1); fma2(acc[2][2],p2,v2); fma2(acc[2][3],p2,v3);
                fma2(acc[3][0],p3,v0); fma2(acc[3][1],p3,v1); fma2(acc[3][2],p3,v2); fma2(acc[3][3],p3,v3);
            }
        }
        __syncthreads();   // protect KP/Vs before next stage
    }

    // Epilogue: normalize, write ctx [b, l, h*64 + c]
    const int b = bh>>2, h = bh&3;
    float* cb = g_CTX + ((size_t)b*LSEQ)*DM + h*HDIM + (tx<<2);
    #pragma unroll
    for (int ip=0; ip<4; ip++){
        float lo[4], hi[4];
        unpack2(acc[ip][0],lo[0],hi[0]); unpack2(acc[ip][1],lo[1],hi[1]);
        unpack2(acc[ip][2],lo[2],hi[2]); unpack2(acc[ip][3],lo[3],hi[3]);
        float inv0 = 1.0f/li[ip<<1], inv1 = 1.0f/li[(ip<<1)+1];
        int r = q0 + (ty<<3) + (ip<<1);
        float4 o0 = make_float4(lo[0]*inv0, lo[1]*inv0, lo[2]*inv0, lo[3]*inv0);
        float4 o1 = make_float4(hi[0]*inv1, hi[1]*inv1, hi[2]*inv1, hi[3]*inv1);
        *(float4*)&cb[(size_t)r*DM]     = o0;
        *(float4*)&cb[(size_t)(r+1)*DM] = o1;
    }
}

// ---------------------------------------------------------------------------
extern "C" void kernel_launch(void* const* d_in, const int* in_sizes, int n_in,
                              void* d_out, int out_size)
{
    const float* x  = (const float*)d_in[0];
    const float* Wq = (const float*)d_in[1];
    const float* bq = (const float*)d_in[2];
    const float* Wk = (const float*)d_in[3];
    const float* bk = (const float*)d_in[4];
    const float* Wv = (const float*)d_in[5];
    const float* bv = (const float*)d_in[6];
    const float* Wo = (const float*)d_in[7];
    const float* bo = (const float*)d_in[8];
    float* out = (float*)d_out;

    // QKV projections -> g_Q/g_K/g_V  (grid.y: 3 mats x 4 col-tiles)
    gemm_qkv<<<dim3(NTOK/128, 12), 256>>>(x, Wq, bq, Wk, bk, Wv, bv);

    // Flash attention -> g_CTX
    cudaFuncSetAttribute(attn_kernel, cudaFuncAttributeMaxDynamicSharedMemorySize, ATTN_SMEM);
    attn_kernel<<<dim3(LSEQ/128, BATCH*NH), 256, ATTN_SMEM>>>();

    // Output projection -> d_out
    gemm_out<<<dim3(NTOK/128, DOUT/64), 256>>>(Wo, bo, out);
}

// round 3
// speedup vs baseline: 1.1377x; 1.0002x over previous
#include <cuda_runtime.h>
#include <stdint.h>

typedef unsigned long long u64;

#define LSEQ 2048
#define BATCH 8
#define NH 4
#define HDIM 64
#define DM 256
#define DOUT 1024
#define NTOK (BATCH*LSEQ)   // 16384
#define QP 132              // SMEM pitch (floats) for transposed tiles

// Scratch (device globals -- no runtime allocation allowed)
__device__ float g_Q[(size_t)BATCH*NH*LSEQ*HDIM];   // [b,h,l,hd]
__device__ float g_K[(size_t)BATCH*NH*LSEQ*HDIM];
__device__ float g_V[(size_t)BATCH*NH*LSEQ*HDIM];
__device__ float g_CTX[(size_t)NTOK*DM];            // [b,l, h*64+j]

// ---------------- packed f32x2 helpers ----------------
__device__ __forceinline__ u64 pack2(float lo, float hi){
    u64 r; asm("mov.b64 %0,{%1,%2};":"=l"(r):"f"(lo),"f"(hi)); return r; }
__device__ __forceinline__ void unpack2(u64 v, float &lo, float &hi){
    asm("mov.b64 {%0,%1},%2;":"=f"(lo),"=f"(hi):"l"(v)); }
__device__ __forceinline__ u64 dup2(float x){ return pack2(x,x); }
__device__ __forceinline__ void fma2(u64 &d, u64 a, u64 b){
    asm("fma.rn.f32x2 %0,%1,%2,%0;":"+l"(d):"l"(a),"l"(b)); }
__device__ __forceinline__ void mul2(u64 &d, u64 a){
    asm("mul.rn.f32x2 %0,%0,%1;":"+l"(d):"l"(a)); }
__device__ __forceinline__ void lds2x64(u64 &x, u64 &y, uint32_t a){
    asm volatile("ld.shared.v2.b64 {%0,%1},[%2];":"=l"(x),"=l"(y):"r"(a)); }
__device__ __forceinline__ void sts64(uint32_t a, u64 v){
    asm volatile("st.shared.b64 [%0],%1;"::"r"(a),"l"(v):"memory"); }

// ===========================================================================
// GEMM: C[M,256]@W[256,N]+b. 128x64 tile, 256 thr, 8x4 microtile, f32x2.
// ===========================================================================
__device__ __forceinline__ void gemm_core(
    const float* __restrict__ A, const float* __restrict__ W, int wstride,
    float* As /*16*QP*/, float* Ws /*16*64*/, int row0, int col0, u64 (&acc)[4][4])
{
    const int tid = threadIdx.x, ty = tid>>4, tx = tid&15;
    const int m0 = tid>>2;               // 0..63
    const int k4 = (tid&3)<<2;           // 0,4,8,12

    const float* ap0 = A + (size_t)(row0+m0)*DM + k4;
    const float* ap1 = ap0 + (size_t)64*DM;
    const int wk = tid>>4, wn = (tid&15)<<2;
    const float* wp = W + (size_t)wk*wstride + col0 + wn;

    uint32_t as_b = (uint32_t)__cvta_generic_to_shared(As);

    float4 ar0 = *(const float4*)ap0;
    float4 ar1 = *(const float4*)ap1;
    float4 wr  = *(const float4*)wp;

    #pragma unroll 1
    for (int k0 = 0; k0 < DM; k0 += 16) {
        As[(k4+0)*QP + m0]      = ar0.x;
        As[(k4+1)*QP + m0]      = ar0.y;
        As[(k4+2)*QP + m0]      = ar0.z;
        As[(k4+3)*QP + m0]      = ar0.w;
        As[(k4+0)*QP + m0 + 64] = ar1.x;
        As[(k4+1)*QP + m0 + 64] = ar1.y;
        As[(k4+2)*QP + m0 + 64] = ar1.z;
        As[(k4+3)*QP + m0 + 64] = ar1.w;
        *(float4*)&Ws[wk*64 + wn] = wr;
        __syncthreads();

        if (k0 + 16 < DM) {   // prefetch next slab
            ar0 = *(const float4*)(ap0 + k0 + 16);
            ar1 = *(const float4*)(ap1 + k0 + 16);
            wr  = *(const float4*)(wp + (size_t)(k0+16)*wstride);
        }

        uint32_t qa = as_b + ty*32;
        #pragma unroll
        for (int kk = 0; kk < 16; kk++) {
            u64 a0,a1,a2,a3;
            lds2x64(a0,a1, qa + kk*(QP*4));
            lds2x64(a2,a3, qa + kk*(QP*4) + 16);
            float4 b4 = *(const float4*)&Ws[kk*64 + (tx<<2)];
            u64 b0=dup2(b4.x), b1=dup2(b4.y), b2=dup2(b4.z), b3=dup2(b4.w);
            fma2(acc[0][0],a0,b0); fma2(acc[0][1],a0,b1); fma2(acc[0][2],a0,b2); fma2(acc[0][3],a0,b3);
            fma2(acc[1][0],a1,b0); fma2(acc[1][1],a1,b1); fma2(acc[1][2],a1,b2); fma2(acc[1][3],a1,b3);
            fma2(acc[2][0],a2,b0); fma2(acc[2][1],a2,b1); fma2(acc[2][2],a2,b2); fma2(acc[2][3],a2,b3);
            fma2(acc[3][0],a3,b0); fma2(acc[3][1],a3,b1); fma2(acc[3][2],a3,b2); fma2(acc[3][3],a3,b3);
        }
        __syncthreads();
    }
}

__global__ __launch_bounds__(256)
void gemm_qkv(const float* __restrict__ x,
              const float* __restrict__ Wq, const float* __restrict__ bq,
              const float* __restrict__ Wk, const float* __restrict__ bk,
              const float* __restrict__ Wv, const float* __restrict__ bv)
{
    __shared__ __align__(16) float As[16*QP];
    __shared__ __align__(16) float Ws[16*64];
    const int tid = threadIdx.x, ty = tid>>4, tx = tid&15;
    const int row0 = blockIdx.x<<7;
    const int yy = blockIdx.y, mat = yy>>2, col0 = (yy&3)<<6;
    const float* W    = (mat==0)?Wq:(mat==1)?Wk:Wv;
    const float* bias = (mat==0)?bq:(mat==1)?bk:bv;
    float* dst        = (mat==0)?g_Q:(mat==1)?g_K:g_V;

    u64 acc[4][4];
    #pragma unroll
    for (int i=0;i<4;i++){ acc[i][0]=0; acc[i][1]=0; acc[i][2]=0; acc[i][3]=0; }

    gemm_core(x, W, DM, As, Ws, row0, col0, acc);

    const int b = row0>>11;
    const int lbase = (row0 & 2047) + (ty<<3);
    float* dbase = dst + ((size_t)(b*NH + (col0>>6))*LSEQ)*HDIM + (tx<<2);
    float4 bb = *(const float4*)&bias[col0 + (tx<<2)];
    #pragma unroll
    for (int ip=0; ip<4; ip++) {
        float lo[4], hi[4];
        unpack2(acc[ip][0],lo[0],hi[0]); unpack2(acc[ip][1],lo[1],hi[1]);
        unpack2(acc[ip][2],lo[2],hi[2]); unpack2(acc[ip][3],lo[3],hi[3]);
        int l = lbase + (ip<<1);
        float4 o0 = make_float4(lo[0]+bb.x, lo[1]+bb.y, lo[2]+bb.z, lo[3]+bb.w);
        float4 o1 = make_float4(hi[0]+bb.x, hi[1]+bb.y, hi[2]+bb.z, hi[3]+bb.w);
        *(float4*)&dbase[(size_t)l*HDIM]     = o0;
        *(float4*)&dbase[(size_t)(l+1)*HDIM] = o1;
    }
}

__global__ __launch_bounds__(256)
void gemm_out(const float* __restrict__ Wo, const float* __restrict__ bo,
              float* __restrict__ C)
{
    __shared__ __align__(16) float As[16*QP];
    __shared__ __align__(16) float Ws[16*64];
    const int tid = threadIdx.x, ty = tid>>4, tx = tid&15;
    const int row0 = blockIdx.x<<7;
    const int col0 = blockIdx.y<<6;

    u64 acc[4][4];
    #pragma unroll
    for (int i=0;i<4;i++){ acc[i][0]=0; acc[i][1]=0; acc[i][2]=0; acc[i][3]=0; }

    gemm_core(g_CTX, Wo, DOUT, As, Ws, row0, col0, acc);

    float4 bb = *(const float4*)&bo[col0 + (tx<<2)];
    const int rbase = row0 + (ty<<3);
    #pragma unroll
    for (int ip=0; ip<4; ip++) {
        float lo[4], hi[4];
        unpack2(acc[ip][0],lo[0],hi[0]); unpack2(acc[ip][1],lo[1],hi[1]);
        unpack2(acc[ip][2],lo[2],hi[2]); unpack2(acc[ip][3],lo[3],hi[3]);
        int r = rbase + (ip<<1);
        float4 o0 = make_float4(lo[0]+bb.x, lo[1]+bb.y, lo[2]+bb.z, lo[3]+bb.w);
        float4 o1 = make_float4(hi[0]+bb.x, hi[1]+bb.y, hi[2]+bb.z, hi[3]+bb.w);
        *(float4*)&C[(size_t)r*DOUT + col0 + (tx<<2)]     = o0;
        *(float4*)&C[(size_t)(r+1)*DOUT + col0 + (tx<<2)] = o1;
    }
}

// ===========================================================================
// Flash attention fp32 + f32x2. Block = (b,h) x 128-query tile, 256 threads.
// Microtile 8(q) x 4(k). SMEM: Qt[d][q], KP = Kt[d][k] then Pt[k][q], Vs[k][d].
// ===========================================================================
#define ATTN_SMEM ((64*QP*2 + 64*64)*4)   // 83968 bytes -> 2 CTAs/SM

__global__ __launch_bounds__(256,2)
void attn_kernel()
{
    extern __shared__ __align__(16) float sm[];
    float* Qt = sm;               // [64][QP]  (d, q)  pre-scaled
    float* KP = sm + 64*QP;       // Kt: [64][QP] (d,k) ; later Pt: [64][QP] (k,q)
    float* Vs = sm + 2*64*QP;     // [64][64]  (k, d)

    uint32_t qt_b = (uint32_t)__cvta_generic_to_shared(Qt);
    uint32_t kp_b = (uint32_t)__cvta_generic_to_shared(KP);

    const int tid = threadIdx.x, ty = tid>>4, tx = tid&15;
    const int q0 = blockIdx.x<<7;
    const int bh = blockIdx.y;

    const float* Qg = g_Q + (size_t)bh*LSEQ*HDIM;
    const float* Kg = g_K + (size_t)bh*LSEQ*HDIM;
    const float* Vg = g_V + (size_t)bh*LSEQ*HDIM;
    const float scale = 0.0625f;   // 1/sqrt(256)

    // Stage Q tile transposed + pre-scaled
    #pragma unroll
    for (int i=0;i<8;i++){
        int e = tid + (i<<8);
        int q = e>>4, d4 = (e&15)<<2;
        float4 v = *(const float4*)(Qg + (size_t)(q0+q)*HDIM + d4);
        Qt[(d4+0)*QP+q] = v.x*scale;
        Qt[(d4+1)*QP+q] = v.y*scale;
        Qt[(d4+2)*QP+q] = v.z*scale;
        Qt[(d4+3)*QP+q] = v.w*scale;
    }

    u64 acc[4][4];
    float mi[8], li[8];
    #pragma unroll
    for (int i=0;i<4;i++){ acc[i][0]=0; acc[i][1]=0; acc[i][2]=0; acc[i][3]=0; }
    #pragma unroll
    for (int i=0;i<8;i++){ mi[i] = -1e30f; li[i] = 0.f; }

    #pragma unroll 1
    for (int kt = 0; kt < LSEQ/64; kt++) {
        const int k0 = kt<<6;

        // Stage K (transposed) + V (natural)
        #pragma unroll
        for (int i=0;i<4;i++){
            int e = tid + (i<<8);
            int k = e>>4, d4 = (e&15)<<2;
            float4 kv = *(const float4*)(Kg + (size_t)(k0+k)*HDIM + d4);
            KP[(d4+0)*QP+k] = kv.x;
            KP[(d4+1)*QP+k] = kv.y;
            KP[(d4+2)*QP+k] = kv.z;
            KP[(d4+3)*QP+k] = kv.w;
            float4 vv = *(const float4*)(Vg + (size_t)(k0+k)*HDIM + d4);
            *(float4*)&Vs[(k<<6)+d4] = vv;
        }
        __syncthreads();

        // S = Q K^T : s2[ip][j] packs q rows (2ip, 2ip+1), col 4tx+j
        u64 s2[4][4];
        #pragma unroll
        for (int i=0;i<4;i++){ s2[i][0]=0; s2[i][1]=0; s2[i][2]=0; s2[i][3]=0; }
        {
            uint32_t qa = qt_b + ty*32;
            #pragma unroll 8
            for (int d=0; d<64; d++){
                u64 a0,a1,a2,a3;
                lds2x64(a0,a1, qa + d*(QP*4));
                lds2x64(a2,a3, qa + d*(QP*4) + 16);
                float4 kb = *(const float4*)&KP[d*QP + (tx<<2)];
                u64 b0=dup2(kb.x), b1=dup2(kb.y), b2=dup2(kb.z), b3=dup2(kb.w);
                fma2(s2[0][0],a0,b0); fma2(s2[0][1],a0,b1); fma2(s2[0][2],a0,b2); fma2(s2[0][3],a0,b3);
                fma2(s2[1][0],a1,b0); fma2(s2[1][1],a1,b1); fma2(s2[1][2],a1,b2); fma2(s2[1][3],a1,b3);
                fma2(s2[2][0],a2,b0); fma2(s2[2][1],a2,b1); fma2(s2[2][2],a2,b2); fma2(s2[2][3],a2,b3);
                fma2(s2[3][0],a3,b0); fma2(s2[3][1],a3,b1); fma2(s2[3][2],a3,b2); fma2(s2[3][3],a3,b3);
            }
        }
        __syncthreads();   // Kt reads done; KP becomes Pt

        // Online softmax (two rows per pair), store Pt transposed [k][q]
        #pragma unroll
        for (int ip=0; ip<4; ip++){
            float l0[4], l1[4];
            unpack2(s2[ip][0],l0[0],l1[0]); unpack2(s2[ip][1],l0[1],l1[1]);
            unpack2(s2[ip][2],l0[2],l1[2]); unpack2(s2[ip][3],l0[3],l1[3]);
            float rm0 = fmaxf(fmaxf(l0[0],l0[1]), fmaxf(l0[2],l0[3]));
            float rm1 = fmaxf(fmaxf(l1[0],l1[1]), fmaxf(l1[2],l1[3]));
            #pragma unroll
            for (int off=8; off>=1; off>>=1){
                rm0 = fmaxf(rm0, __shfl_xor_sync(0xffffffffu, rm0, off));
                rm1 = fmaxf(rm1, __shfl_xor_sync(0xffffffffu, rm1, off));
            }
            const int r0 = ip<<1, r1 = (ip<<1)+1;
            float mn0 = fmaxf(mi[r0], rm0), mn1 = fmaxf(mi[r1], rm1);
            float c0 = __expf(mi[r0]-mn0),  c1 = __expf(mi[r1]-mn1);
            mi[r0]=mn0; mi[r1]=mn1;
            float rs0=0.f, rs1=0.f;
            #pragma unroll
            for (int j=0;j<4;j++){
                l0[j] = __expf(l0[j]-mn0); rs0 += l0[j];
                l1[j] = __expf(l1[j]-mn1); rs1 += l1[j];
            }
            #pragma unroll
            for (int off=8; off>=1; off>>=1){
                rs0 += __shfl_xor_sync(0xffffffffu, rs0, off);
                rs1 += __shfl_xor_sync(0xffffffffu, rs1, off);
            }
            li[r0] = li[r0]*c0 + rs0;
            li[r1] = li[r1]*c1 + rs1;
            u64 c2 = pack2(c0, c1);
            mul2(acc[ip][0],c2); mul2(acc[ip][1],c2); mul2(acc[ip][2],c2); mul2(acc[ip][3],c2);
            // Pt[k=4tx+j][q = 8ty+2ip (+1)]
            uint32_t pa = kp_b + (((tx<<2))*QP + (ty<<3) + (ip<<1))*4;
            sts64(pa,           pack2(l0[0],l1[0]));
            sts64(pa + QP*4,    pack2(l0[1],l1[1]));
            sts64(pa + QP*8,    pack2(l0[2],l1[2]));
            sts64(pa + QP*12,   pack2(l0[3],l1[3]));
        }
        __syncthreads();

        // acc += P @ V
        {
            uint32_t pa2 = kp_b + ty*32;
            #pragma unroll 8
            for (int k=0; k<64; k++){
                u64 p0,p1,p2,p3;
                lds2x64(p0,p1, pa2 + k*(QP*4));
                lds2x64(p2,p3, pa2 + k*(QP*4) + 16);
                float4 vv = *(const float4*)&Vs[(k<<6) + (tx<<2)];
                u64 v0=dup2(vv.x), v1=dup2(vv.y), v2=dup2(vv.z), v3=dup2(vv.w);
                fma2(acc[0][0],p0,v0); fma2(acc[0][1],p0,v1); fma2(acc[0][2],p0,v2); fma2(acc[0][3],p0,v3);
                fma2(acc[1][0],p1,v0); fma2(acc[1][1],p1,v1); fma2(acc[1][2],p1,v2); fma2(acc[1][3],p1,v3);
                fma2(acc[2][0],p2,v0); fma2(acc[2][1],p2,v1); fma2(acc[2][2],p2,v2); fma2(acc[2][3],p2,v3);
                fma2(acc[3][0],p3,v0); fma2(acc[3][1],p3,v1); fma2(acc[3][2],p3,v2); fma2(acc[3][3],p3,v3);
            }
        }
        __syncthreads();   // protect KP/Vs before next stage
    }

    // Epilogue: normalize, write ctx [b, l, h*64 + c]
    const int b = bh>>2, h = bh&3;
    float* cb = g_CTX + ((size_t)b*LSEQ)*DM + h*HDIM + (tx<<2);
    #pragma unroll
    for (int ip=0; ip<4; ip++){
        float lo[4], hi[4];
        unpack2(acc[ip][0],lo[0],hi[0]); unpack2(acc[ip][1],lo[1],hi[1]);
        unpack2(acc[ip][2],lo[2],hi[2]); unpack2(acc[ip][3],lo[3],hi[3]);
        float inv0 = 1.0f/li[ip<<1], inv1 = 1.0f/li[(ip<<1)+1];
        int r = q0 + (ty<<3) + (ip<<1);
        float4 o0 = make_float4(lo[0]*inv0, lo[1]*inv0, lo[2]*inv0, lo[3]*inv0);
        float4 o1 = make_float4(hi[0]*inv1, hi[1]*inv1, hi[2]*inv1, hi[3]*inv1);
        *(float4*)&cb[(size_t)r*DM]     = o0;
        *(float4*)&cb[(size_t)(r+1)*DM] = o1;
    }
}

// ---------------------------------------------------------------------------
extern "C" void kernel_launch(void* const* d_in, const int* in_sizes, int n_in,
                              void* d_out, int out_size)
{
    const float* x  = (const float*)d_in[0];
    const float* Wq = (const float*)d_in[1];
    const float* bq = (const float*)d_in[2];
    const float* Wk = (const float*)d_in[3];
    const float* bk = (const float*)d_in[4];
    const float* Wv = (const float*)d_in[5];
    const float* bv = (const float*)d_in[6];
    const float* Wo = (const float*)d_in[7];
    const float* bo = (const float*)d_in[8];
    float* out = (float*)d_out;

    // QKV projections -> g_Q/g_K/g_V  (grid.y: 3 mats x 4 col-tiles)
    gemm_qkv<<<dim3(NTOK/128, 12), 256>>>(x, Wq, bq, Wk, bk, Wv, bv);

    // Flash attention -> g_CTX
    cudaFuncSetAttribute(attn_kernel, cudaFuncAttributeMaxDynamicSharedMemorySize, ATTN_SMEM);
    attn_kernel<<<dim3(LSEQ/128, BATCH*NH), 256, ATTN_SMEM>>>();

    // Output projection -> d_out
    gemm_out<<<dim3(NTOK/128, DOUT/64), 256>>>(Wo, bo, out);
}

// round 5
// speedup vs baseline: 2.1610x; 1.8995x over previous
#include <cuda_runtime.h>
#include <stdint.h>

typedef unsigned long long u64;

#define LSEQ 2048
#define BATCH 8
#define NH 4
#define NBH (BATCH*NH)      // 32
#define HDIM 64
#define DM 256
#define DOUT 1024
#define NTOK (BATCH*LSEQ)   // 16384
#define QP 132              // SMEM pitch (floats) for SIMT GEMM

// ---------------- device scratch (no runtime alloc allowed) ----------------
__device__ __align__(16) unsigned short g_Qh[(size_t)NBH*LSEQ*HDIM];  // bf16, pre-scaled by log2e/16
__device__ __align__(16) unsigned short g_Ql[(size_t)NBH*LSEQ*HDIM];
__device__ __align__(16) unsigned short g_Kh[(size_t)NBH*LSEQ*HDIM];
__device__ __align__(16) unsigned short g_Kl[(size_t)NBH*LSEQ*HDIM];
__device__ __align__(16) float          g_V [(size_t)NBH*LSEQ*HDIM];  // fp32 natural [bh][l][d]
__device__ __align__(16) unsigned short g_Vth[(size_t)NBH*HDIM*LSEQ]; // bf16 [bh][d][l]
__device__ __align__(16) unsigned short g_Vtl[(size_t)NBH*HDIM*LSEQ];
__device__ __align__(16) float          g_CTX[(size_t)NTOK*DM];       // [b,l, h*64+j]

// ---------------- scalar helpers ----------------
__device__ __forceinline__ u64 pack2(float lo, float hi){
    u64 r; asm("mov.b64 %0,{%1,%2};":"=l"(r):"f"(lo),"f"(hi)); return r; }
__device__ __forceinline__ void unpack2(u64 v, float &lo, float &hi){
    asm("mov.b64 {%0,%1},%2;":"=f"(lo),"=f"(hi):"l"(v)); }
__device__ __forceinline__ u64 dup2(float x){ return pack2(x,x); }
__device__ __forceinline__ void fma2(u64 &d, u64 a, u64 b){
    asm("fma.rn.f32x2 %0,%1,%2,%0;":"+l"(d):"l"(a),"l"(b)); }
__device__ __forceinline__ void lds2x64(u64 &x, u64 &y, uint32_t a){
    asm volatile("ld.shared.v2.b64 {%0,%1},[%2];":"=l"(x),"=l"(y):"r"(a)); }

// round-to-nearest-even bf16 split: x ~= hi + lo (each bf16)
__device__ __forceinline__ void bsplit(float x, uint32_t &h16, uint32_t &l16){
    uint32_t u = __float_as_uint(x);
    uint32_t rh = u + 0x7fffu + ((u>>16)&1u);
    h16 = rh >> 16;
    float xl = x - __uint_as_float(rh & 0xffff0000u);
    uint32_t v = __float_as_uint(xl);
    l16 = (v + 0x7fffu + ((v>>16)&1u)) >> 16;
}

__device__ __forceinline__ float ex2f(float x){
    float r; asm("ex2.approx.f32 %0,%1;":"=f"(r):"f"(x)); return r; }
__device__ __forceinline__ uint32_t prmt_hi(uint32_t a, uint32_t b){
    uint32_t r; asm("prmt.b32 %0,%1,%2,0x7632;":"=r"(r):"r"(a),"r"(b)); return r; }
// packed bf16x2 = {lo, hi}
__device__ __forceinline__ uint32_t cvt2(float lo, float hi){
    uint32_t r; asm("cvt.rn.bf16x2.f32 %0,%1,%2;":"=r"(r):"f"(hi),"f"(lo)); return r; }

// ---------------- warp-MMA primitives (baseline sm_80+ PTX) ----------------
__device__ __forceinline__ void ldsm4(uint32_t &r0, uint32_t &r1, uint32_t &r2, uint32_t &r3, uint32_t addr){
    asm volatile("ldmatrix.sync.aligned.m8n8.x4.shared.b16 {%0,%1,%2,%3},[%4];"
        : "=r"(r0),"=r"(r1),"=r"(r2),"=r"(r3) : "r"(addr));
}
__device__ __forceinline__ void mma_bf16(float* d, const uint32_t* a, uint32_t b0, uint32_t b1){
    asm volatile("mma.sync.aligned.m16n8k16.row.col.f32.bf16.bf16.f32 "
        "{%0,%1,%2,%3},{%4,%5,%6,%7},{%8,%9},{%0,%1,%2,%3};"
        : "+f"(d[0]),"+f"(d[1]),"+f"(d[2]),"+f"(d[3])
        : "r"(a[0]),"r"(a[1]),"r"(a[2]),"r"(a[3]),"r"(b0),"r"(b1));
}
__device__ __forceinline__ uint32_t swz(uint32_t o){ return o ^ ((o>>3)&0x70u); }

// ===========================================================================
// SIMT GEMM core (known-good from R2)
// ===========================================================================
__device__ __forceinline__ void gemm_core(
    const float* __restrict__ A, const float* __restrict__ W, int wstride,
    float* As, float* Ws, int row0, int col0, u64 (&acc)[4][4])
{
    const int tid = threadIdx.x, ty = tid>>4, tx = tid&15;
    const int m0 = tid>>2;
    const int k4 = (tid&3)<<2;
    const float* ap0 = A + (size_t)(row0 + m0)*DM + k4;
    const float* ap1 = ap0 + (size_t)64*DM;
    const int wk = tid>>4, wn = (tid&15)<<2;
    const float* wp = W + (size_t)wk*wstride + col0 + wn;
    uint32_t as_b = (uint32_t)__cvta_generic_to_shared(As);
    float4 ar0 = *(const float4*)ap0;
    float4 ar1 = *(const float4*)ap1;
    float4 wr  = *(const float4*)wp;
    #pragma unroll 1
    for (int k0 = 0; k0 < DM; k0 += 16) {
        As[(k4+0)*QP+m0]    = ar0.x; As[(k4+1)*QP+m0]    = ar0.y;
        As[(k4+2)*QP+m0]    = ar0.z; As[(k4+3)*QP+m0]    = ar0.w;
        As[(k4+0)*QP+m0+64] = ar1.x; As[(k4+1)*QP+m0+64] = ar1.y;
        As[(k4+2)*QP+m0+64] = ar1.z; As[(k4+3)*QP+m0+64] = ar1.w;
        *(float4*)&Ws[wk*64+wn] = wr;
        __syncthreads();
        if (k0 + 16 < DM) {
            ar0 = *(const float4*)(ap0 + k0 + 16);
            ar1 = *(const float4*)(ap1 + k0 + 16);
            wr  = *(const float4*)(wp + (size_t)(k0+16)*wstride);
        }
        uint32_t qa = as_b + ty*32;
        #pragma unroll
        for (int kk = 0; kk < 16; kk++) {
            u64 a0,a1,a2,a3;
            lds2x64(a0,a1, qa + kk*(QP*4));
            lds2x64(a2,a3, qa + kk*(QP*4) + 16);
            float4 b4 = *(const float4*)&Ws[kk*64 + (tx<<2)];
            u64 b0=dup2(b4.x), b1=dup2(b4.y), b2=dup2(b4.z), b3=dup2(b4.w);
            fma2(acc[0][0],a0,b0); fma2(acc[0][1],a0,b1); fma2(acc[0][2],a0,b2); fma2(acc[0][3],a0,b3);
            fma2(acc[1][0],a1,b0); fma2(acc[1][1],a1,b1); fma2(acc[1][2],a1,b2); fma2(acc[1][3],a1,b3);
            fma2(acc[2][0],a2,b0); fma2(acc[2][1],a2,b1); fma2(acc[2][2],a2,b2); fma2(acc[2][3],a2,b3);
            fma2(acc[3][0],a3,b0); fma2(acc[3][1],a3,b1); fma2(acc[3][2],a3,b2); fma2(acc[3][3],a3,b3);
        }
        __syncthreads();
    }
}

// QKV projection. Q/K -> split bf16 (Q pre-scaled by log2e/16); V -> fp32.
__global__ __launch_bounds__(256)
void gemm_qkv(const float* __restrict__ x,
              const float* __restrict__ Wq, const float* __restrict__ bq,
              const float* __restrict__ Wk, const float* __restrict__ bk,
              const float* __restrict__ Wv, const float* __restrict__ bv)
{
    __shared__ __align__(16) float As[16*QP];
    __shared__ __align__(16) float Ws[16*64];
    const int tid = threadIdx.x, ty = tid>>4, tx = tid&15;
    const int row0 = blockIdx.x<<7;
    const int yy = blockIdx.y, mat = yy>>2, col0 = (yy&3)<<6;
    const float* W    = (mat==0)?Wq:(mat==1)?Wk:Wv;
    const float* bias = (mat==0)?bq:(mat==1)?bk:bv;

    u64 acc[4][4];
    #pragma unroll
    for (int i=0;i<4;i++){ acc[i][0]=0; acc[i][1]=0; acc[i][2]=0; acc[i][3]=0; }
    gemm_core(x, W, DM, As, Ws, row0, col0, acc);

    const int b = row0>>11, h = col0>>6;
    const int lbase = (row0 & 2047) + (ty<<3);
    float4 bb = *(const float4*)&bias[col0 + (tx<<2)];
    const float scl = (mat==0) ? 0.09016844f : 1.0f;   // log2e/16 for Q

    if (mat < 2) {
        unsigned short* dh = (mat==0) ? g_Qh : g_Kh;
        unsigned short* dl = (mat==0) ? g_Ql : g_Kl;
        #pragma unroll
        for (int ip=0; ip<4; ip++){
            float lo[4], hi[4];
            unpack2(acc[ip][0],lo[0],hi[0]); unpack2(acc[ip][1],lo[1],hi[1]);
            unpack2(acc[ip][2],lo[2],hi[2]); unpack2(acc[ip][3],lo[3],hi[3]);
            int l = lbase + (ip<<1);
            float v0[4] = {(lo[0]+bb.x)*scl,(lo[1]+bb.y)*scl,(lo[2]+bb.z)*scl,(lo[3]+bb.w)*scl};
            float v1[4] = {(hi[0]+bb.x)*scl,(hi[1]+bb.y)*scl,(hi[2]+bb.z)*scl,(hi[3]+bb.w)*scl};
            size_t base0 = ((size_t)(b*NH+h)*LSEQ + l)*HDIM + (tx<<2);
            #pragma unroll
            for (int r=0; r<2; r++){
                float* vv = r ? v1 : v0;
                uint32_t h0,l0,h1,l1,h2,l2,h3,l3;
                bsplit(vv[0],h0,l0); bsplit(vv[1],h1,l1);
                bsplit(vv[2],h2,l2); bsplit(vv[3],h3,l3);
                uint2 H = make_uint2(h0|(h1<<16), h2|(h3<<16));
                uint2 L = make_uint2(l0|(l1<<16), l2|(l3<<16));
                *(uint2*)&dh[base0 + (size_t)r*HDIM] = H;
                *(uint2*)&dl[base0 + (size_t)r*HDIM] = L;
            }
        }
    } else {
        float* dbase = g_V + ((size_t)(b*NH+h)*LSEQ)*HDIM + (tx<<2);
        #pragma unroll
        for (int ip=0; ip<4; ip++){
            float lo[4], hi[4];
            unpack2(acc[ip][0],lo[0],hi[0]); unpack2(acc[ip][1],lo[1],hi[1]);
            unpack2(acc[ip][2],lo[2],hi[2]); unpack2(acc[ip][3],lo[3],hi[3]);
            int l = lbase + (ip<<1);
            float4 o0 = make_float4(lo[0]+bb.x, lo[1]+bb.y, lo[2]+bb.z, lo[3]+bb.w);
            float4 o1 = make_float4(hi[0]+bb.x, hi[1]+bb.y, hi[2]+bb.z, hi[3]+bb.w);
            *(float4*)&dbase[(size_t)l*HDIM]     = o0;
            *(float4*)&dbase[(size_t)(l+1)*HDIM] = o1;
        }
    }
}

// V transpose + split: g_V [bh][l][d] fp32 -> g_Vth/g_Vtl [bh][d][l] bf16
__global__ __launch_bounds__(256)
void vsplit_t()
{
    __shared__ float ts[64][65];
    const int tid = threadIdx.x;
    const int l0 = blockIdx.x<<6;
    const int bh = blockIdx.y;
    const float* src = g_V + ((size_t)bh*LSEQ + l0)*HDIM;
    #pragma unroll
    for (int i=0;i<16;i++){
        int e = tid + (i<<8);
        int r = e>>6, c = e&63;
        ts[c][r] = src[(size_t)r*HDIM + c];
    }
    __syncthreads();
    uint32_t* dh = (uint32_t*)g_Vth;
    uint32_t* dl = (uint32_t*)g_Vtl;
    #pragma unroll
    for (int i=0;i<8;i++){
        int f = tid + (i<<8);
        int d = f>>5, kp = f&31;
        float a = ts[d][kp*2], b2 = ts[d][kp*2+1];
        uint32_t ha,la,hb,lb;
        bsplit(a,ha,la); bsplit(b2,hb,lb);
        size_t o = ((size_t)bh*HDIM + d)*(LSEQ/2) + (l0>>1) + kp;
        dh[o] = ha | (hb<<16);
        dl[o] = la | (lb<<16);
    }
}

// ===========================================================================
// Warp-MMA flash attention (one-pass, no max subtraction; 3-term split bf16)
// Block = (bh, 128-query tile), 256 threads = 8 warps x 16 q-rows.
// SMEM: Qh(16K) Ql(16K) | Kh(8K) Kl(8K) Vh(8K) Vl(8K) = 64KB (swizzled 128B rows)
// ===========================================================================
#define SQH 0
#define SQL 16384
#define SKH 32768
#define SKL 40960
#define SVH 49152
#define SVL 57344
#define ATTN_SMEM 65536

__global__ __launch_bounds__(256,2)
void attn_mma()
{
    extern __shared__ __align__(128) char smem[];
    const uint32_t sb = (uint32_t)__cvta_generic_to_shared(smem);
    const int tid = threadIdx.x, lane = tid&31, wid = tid>>5;
    const int q0 = blockIdx.x<<7;
    const int bh = blockIdx.y;

    const char* gqh = (const char*)g_Qh;
    const char* gql = (const char*)g_Ql;
    const char* gkh = (const char*)g_Kh;
    const char* gkl = (const char*)g_Kl;
    const char* gvh = (const char*)g_Vth;
    const char* gvl = (const char*)g_Vtl;
    const size_t bhb = (size_t)bh*LSEQ*HDIM*2;   // 262144 bytes for all six arrays

    // ---- stage Q (Qh,Ql): 128 rows x 128B each, swizzled ----
    #pragma unroll
    for (int i=0;i<8;i++){
        int idx = tid + (i<<8);           // 0..2047
        int arr = idx>>10, c = idx&1023, row = c>>3, j = c&7;
        uint4 v = *(const uint4*)((arr?gql:gqh) + bhb + (size_t)(q0+row)*128 + j*16);
        *(uint4*)(smem + (arr?SQL:SQH) + swz(row*128 + j*16)) = v;
    }
    __syncthreads();

    // ---- load Qh A-fragments to registers (16 q-rows per warp, 4 k-steps) ----
    const int qr0 = wid<<4;
    const uint32_t lrow = (uint32_t)(lane&15)*128 + (uint32_t)(lane&16);  // row*128 + half-col
    uint32_t qh[4][4];
    #pragma unroll
    for (int c=0;c<4;c++)
        ldsm4(qh[c][0],qh[c][1],qh[c][2],qh[c][3],
              sb + SQH + swz((uint32_t)qr0*128 + lrow + c*32));

    float o[8][4];
    #pragma unroll
    for (int j=0;j<8;j++){ o[j][0]=0.f;o[j][1]=0.f;o[j][2]=0.f;o[j][3]=0.f; }
    float lsum0 = 0.f, lsum1 = 0.f;

    #pragma unroll 1
    for (int kt = 0; kt < LSEQ/64; kt++) {
        const int k0 = kt<<6;
        __syncthreads();   // prior tile fully consumed
        // ---- stage Kh,Kl ([key][d], 128B rows) and Vh,Vl ([d][keys] slice) ----
        #pragma unroll
        for (int i=0;i<8;i++){
            int idx = tid + (i<<8);       // 0..2047
            int arr = idx>>9, c = idx&511, row = c>>3, j = c&7;
            const char* s; uint32_t off;
            if      (arr==0){ s = gkh + bhb + (size_t)(k0+row)*128 + j*16; off = SKH; }
            else if (arr==1){ s = gkl + bhb + (size_t)(k0+row)*128 + j*16; off = SKL; }
            else if (arr==2){ s = gvh + bhb + (size_t)row*4096 + k0*2 + j*16; off = SVH; }
            else            { s = gvl + bhb + (size_t)row*4096 + k0*2 + j*16; off = SVL; }
            uint4 v = *(const uint4*)s;
            *(uint4*)(smem + off + swz(row*128 + j*16)) = v;
        }
        __syncthreads();

        // ---- S = Qh*Kh + Qh*Kl + Ql*Kh  (16q x 64keys per warp) ----
        float s[8][4];
        #pragma unroll
        for (int j=0;j<8;j++){ s[j][0]=0.f;s[j][1]=0.f;s[j][2]=0.f;s[j][3]=0.f; }
        #pragma unroll
        for (int c=0;c<4;c++){
            uint32_t ql[4];
            ldsm4(ql[0],ql[1],ql[2],ql[3], sb + SQL + swz((uint32_t)qr0*128 + lrow + c*32));
            #pragma unroll
            for (int p=0;p<4;p++){
                uint32_t kh0,kh1,kh2,kh3, kl0,kl1,kl2,kl3;
                uint32_t boff = swz((uint32_t)(p<<11) + lrow + c*32);
                ldsm4(kh0,kh1,kh2,kh3, sb + SKH + boff);
                ldsm4(kl0,kl1,kl2,kl3, sb + SKL + boff);
                mma_bf16(s[2*p],   qh[c], kh0, kh2);
                mma_bf16(s[2*p+1], qh[c], kh1, kh3);
                mma_bf16(s[2*p],   qh[c], kl0, kl2);
                mma_bf16(s[2*p+1], qh[c], kl1, kl3);
                mma_bf16(s[2*p],   ql,    kh0, kh2);
                mma_bf16(s[2*p+1], ql,    kh1, kh3);
            }
        }

        // ---- epilogue: exp2, rowsum, split into P A-fragments (in-register) ----
        uint32_t ph[4][4], pl[4][4];
        #pragma unroll
        for (int j=0;j<8;j++){
            float p0 = ex2f(s[j][0]), p1 = ex2f(s[j][1]);
            float p2 = ex2f(s[j][2]), p3 = ex2f(s[j][3]);
            lsum0 += p0 + p1;  lsum1 += p2 + p3;
            uint32_t u0=__float_as_uint(p0), u1=__float_as_uint(p1);
            uint32_t u2=__float_as_uint(p2), u3=__float_as_uint(p3);
            int c = j>>1, r = (j&1)<<1;
            ph[c][r+0] = prmt_hi(u0,u1);
            ph[c][r+1] = prmt_hi(u2,u3);
            pl[c][r+0] = cvt2(p0 - __uint_as_float(u0&0xffff0000u),
                              p1 - __uint_as_float(u1&0xffff0000u));
            pl[c][r+1] = cvt2(p2 - __uint_as_float(u2&0xffff0000u),
                              p3 - __uint_as_float(u3&0xffff0000u));
        }

        // ---- O += Ph*Vh + Ph*Vl + Pl*Vh ----
        #pragma unroll
        for (int c=0;c<4;c++){
            #pragma unroll
            for (int p=0;p<4;p++){
                uint32_t vh0,vh1,vh2,vh3, vl0,vl1,vl2,vl3;
                uint32_t boff = swz((uint32_t)(p<<11) + lrow + c*32);
                ldsm4(vh0,vh1,vh2,vh3, sb + SVH + boff);
                ldsm4(vl0,vl1,vl2,vl3, sb + SVL + boff);
                mma_bf16(o[2*p],   ph[c], vh0, vh2);
                mma_bf16(o[2*p+1], ph[c], vh1, vh3);
                mma_bf16(o[2*p],   ph[c], vl0, vl2);
                mma_bf16(o[2*p+1], ph[c], vl1, vl3);
                mma_bf16(o[2*p],   pl[c], vh0, vh2);
                mma_bf16(o[2*p+1], pl[c], vh1, vh3);
            }
        }
    }

    // ---- finalize: quad-reduce rowsums, normalize, store ctx ----
    lsum0 += __shfl_xor_sync(0xffffffffu, lsum0, 1);
    lsum0 += __shfl_xor_sync(0xffffffffu, lsum0, 2);
    lsum1 += __shfl_xor_sync(0xffffffffu, lsum1, 1);
    lsum1 += __shfl_xor_sync(0xffffffffu, lsum1, 2);
    const float inv0 = 1.0f/lsum0, inv1 = 1.0f/lsum1;

    const int b = bh>>2, h = bh&3;
    const int r0 = q0 + qr0 + (lane>>2);
    float* cb = g_CTX + ((size_t)b*LSEQ)*DM + h*HDIM + ((lane&3)<<1);
    #pragma unroll
    for (int j=0;j<8;j++){
        *(float2*)&cb[(size_t)r0*DM     + 8*j] = make_float2(o[j][0]*inv0, o[j][1]*inv0);
        *(float2*)&cb[(size_t)(r0+8)*DM + 8*j] = make_float2(o[j][2]*inv1, o[j][3]*inv1);
    }
}

// ===========================================================================
__global__ __launch_bounds__(256)
void gemm_out(const float* __restrict__ Wo, const float* __restrict__ bo,
              float* __restrict__ C)
{
    __shared__ __align__(16) float As[16*QP];
    __shared__ __align__(16) float Ws[16*64];
    const int tid = threadIdx.x, ty = tid>>4, tx = tid&15;
    const int row0 = blockIdx.x<<7;
    const int col0 = blockIdx.y<<6;
    u64 acc[4][4];
    #pragma unroll
    for (int i=0;i<4;i++){ acc[i][0]=0; acc[i][1]=0; acc[i][2]=0; acc[i][3]=0; }
    gemm_core(g_CTX, Wo, DOUT, As, Ws, row0, col0, acc);
    float4 bb = *(const float4*)&bo[col0 + (tx<<2)];
    const int rbase = row0 + (ty<<3);
    #pragma unroll
    for (int ip=0; ip<4; ip++){
        float lo[4], hi[4];
        unpack2(acc[ip][0],lo[0],hi[0]); unpack2(acc[ip][1],lo[1],hi[1]);
        unpack2(acc[ip][2],lo[2],hi[2]); unpack2(acc[ip][3],lo[3],hi[3]);
        int r = rbase + (ip<<1);
        float4 o0 = make_float4(lo[0]+bb.x, lo[1]+bb.y, lo[2]+bb.z, lo[3]+bb.w);
        float4 o1 = make_float4(hi[0]+bb.x, hi[1]+bb.y, hi[2]+bb.z, hi[3]+bb.w);
        *(float4*)&C[(size_t)r*DOUT + col0 + (tx<<2)]     = o0;
        *(float4*)&C[(size_t)(r+1)*DOUT + col0 + (tx<<2)] = o1;
    }
}

// ---------------------------------------------------------------------------
extern "C" void kernel_launch(void* const* d_in, const int* in_sizes, int n_in,
                              void* d_out, int out_size)
{
    const float* x  = (const float*)d_in[0];
    const float* Wq = (const float*)d_in[1];
    const float* bq = (const float*)d_in[2];
    const float* Wk = (const float*)d_in[3];
    const float* bk = (const float*)d_in[4];
    const float* Wv = (const float*)d_in[5];
    const float* bv = (const float*)d_in[6];
    const float* Wo = (const float*)d_in[7];
    const float* bo = (const float*)d_in[8];
    float* out = (float*)d_out;

    gemm_qkv<<<dim3(NTOK/128, 12), 256>>>(x, Wq, bq, Wk, bk, Wv, bv);
    vsplit_t<<<dim3(LSEQ/64, NBH), 256>>>();

    cudaFuncSetAttribute(attn_mma, cudaFuncAttributeMaxDynamicSharedMemorySize, ATTN_SMEM);
    attn_mma<<<dim3(LSEQ/128, NBH), 256, ATTN_SMEM>>>();

    gemm_out<<<dim3(NTOK/128, DOUT/64), 256>>>(Wo, bo, out);
}

// round 6
// speedup vs baseline: 2.6883x; 1.2440x over previous
#include <cuda_runtime.h>
#include <stdint.h>

typedef unsigned long long u64;

#define LSEQ 2048
#define BATCH 8
#define NH 4
#define NBH (BATCH*NH)      // 32
#define HDIM 64
#define DM 256
#define DOUT 1024
#define NTOK (BATCH*LSEQ)   // 16384

// ---------------- device scratch (no runtime alloc allowed) ----------------
__device__ __align__(16) unsigned short g_Qh[(size_t)NBH*LSEQ*HDIM];  // bf16, pre-scaled by log2e/16
__device__ __align__(16) unsigned short g_Ql[(size_t)NBH*LSEQ*HDIM];
__device__ __align__(16) unsigned short g_Kh[(size_t)NBH*LSEQ*HDIM];
__device__ __align__(16) unsigned short g_Kl[(size_t)NBH*LSEQ*HDIM];
__device__ __align__(16) float          g_V [(size_t)NBH*LSEQ*HDIM];  // fp32 [bh][l][d]
__device__ __align__(16) unsigned short g_Vth[(size_t)NBH*HDIM*LSEQ]; // bf16 [bh][d][l]
__device__ __align__(16) unsigned short g_Vtl[(size_t)NBH*HDIM*LSEQ];
__device__ __align__(16) unsigned short g_xh[(size_t)NTOK*DM];        // split x
__device__ __align__(16) unsigned short g_xl[(size_t)NTOK*DM];
__device__ __align__(16) unsigned short g_CXh[(size_t)NTOK*DM];       // split ctx [b,l,h*64+j]
__device__ __align__(16) unsigned short g_CXl[(size_t)NTOK*DM];
#define WROWS (3*DM + DOUT)   // 1792 rows of W^T (qkv then out)
__device__ __align__(16) unsigned short g_Wh[(size_t)WROWS*DM];       // W^T split [n][k]
__device__ __align__(16) unsigned short g_Wl[(size_t)WROWS*DM];

// ---------------- scalar helpers ----------------
__device__ __forceinline__ void bsplit(float x, uint32_t &h16, uint32_t &l16){
    uint32_t u = __float_as_uint(x);
    uint32_t rh = u + 0x7fffu + ((u>>16)&1u);
    h16 = rh >> 16;
    float xl = x - __uint_as_float(rh & 0xffff0000u);
    uint32_t v = __float_as_uint(xl);
    l16 = (v + 0x7fffu + ((v>>16)&1u)) >> 16;
}
__device__ __forceinline__ uint32_t bpack(float a, float b){
    uint32_t ha,la,hb,lb_unused; (void)lb_unused;
    uint32_t u=__float_as_uint(a), v=__float_as_uint(b);
    ha = (u + 0x7fffu + ((u>>16)&1u)) & 0xffff0000u;
    hb = (v + 0x7fffu + ((v>>16)&1u)) >> 16;
    la = 0; (void)la;
    return (ha>>16) | (hb<<16);
}
__device__ __forceinline__ float ex2f(float x){
    float r; asm("ex2.approx.f32 %0,%1;":"=f"(r):"f"(x)); return r; }
__device__ __forceinline__ uint32_t prmt_hi(uint32_t a, uint32_t b){
    uint32_t r; asm("prmt.b32 %0,%1,%2,0x7632;":"=r"(r):"r"(a),"r"(b)); return r; }
__device__ __forceinline__ uint32_t cvt2(float lo, float hi){
    uint32_t r; asm("cvt.rn.bf16x2.f32 %0,%1,%2;":"=r"(r):"f"(hi),"f"(lo)); return r; }

// ---------------- warp-MMA primitives ----------------
__device__ __forceinline__ void ldsm4(uint32_t &r0, uint32_t &r1, uint32_t &r2, uint32_t &r3, uint32_t addr){
    asm volatile("ldmatrix.sync.aligned.m8n8.x4.shared.b16 {%0,%1,%2,%3},[%4];"
        : "=r"(r0),"=r"(r1),"=r"(r2),"=r"(r3) : "r"(addr));
}
__device__ __forceinline__ void mma_bf16(float* d, const uint32_t* a, uint32_t b0, uint32_t b1){
    asm volatile("mma.sync.aligned.m16n8k16.row.col.f32.bf16.bf16.f32 "
        "{%0,%1,%2,%3},{%4,%5,%6,%7},{%8,%9},{%0,%1,%2,%3};"
        : "+f"(d[0]),"+f"(d[1]),"+f"(d[2]),"+f"(d[3])
        : "r"(a[0]),"r"(a[1]),"r"(a[2]),"r"(a[3]),"r"(b0),"r"(b1));
}
__device__ __forceinline__ uint32_t swz(uint32_t o){ return o ^ ((o>>3)&0x70u); }

// ===========================================================================
// Prep: split x into bf16 hi/lo
// ===========================================================================
__global__ __launch_bounds__(256)
void xsplit(const float* __restrict__ x)
{
    uint32_t* xh = (uint32_t*)g_xh;
    uint32_t* xl = (uint32_t*)g_xl;
    size_t p0 = (size_t)blockIdx.x*1024 + threadIdx.x;
    #pragma unroll
    for (int i=0;i<4;i++){
        size_t p = p0 + (size_t)i*256;
        float2 v = ((const float2*)x)[p];
        uint32_t ha,la,hb,lb;
        bsplit(v.x,ha,la); bsplit(v.y,hb,lb);
        xh[p] = ha | (hb<<16);
        xl[p] = la | (lb<<16);
    }
}

// Prep: W^T split. qkv (3 x 256x256) then Wo (256x1024). Output rows [n][k].
__global__ __launch_bounds__(256)
void wsplit(const float* __restrict__ Wq, const float* __restrict__ Wk,
            const float* __restrict__ Wv, const float* __restrict__ Wo)
{
    __shared__ float ts[64][65];
    const int tid = threadIdx.x;
    int bx = blockIdx.x;
    const float* W; int N, kt0, nt0, rowbase;
    if (bx < 48) {
        int mat = bx/16, t = bx%16;
        W = (mat==0)?Wq:(mat==1)?Wk:Wv; N = DM;
        kt0 = (t>>2)<<6; nt0 = (t&3)<<6; rowbase = mat*DM + nt0;
    } else {
        bx -= 48;
        W = Wo; N = DOUT;
        kt0 = (bx&3)<<6; nt0 = (bx>>2)<<6; rowbase = 3*DM + nt0;
    }
    #pragma unroll
    for (int i=0;i<16;i++){
        int e = tid + (i<<8);
        int k = e>>6, n = e&63;
        ts[n][k] = W[(size_t)(kt0+k)*N + nt0 + n];
    }
    __syncthreads();
    uint32_t* wh = (uint32_t*)g_Wh;
    uint32_t* wl = (uint32_t*)g_Wl;
    #pragma unroll
    for (int i=0;i<8;i++){
        int e = tid + (i<<8);
        int n = e>>5, kp = e&31;
        float a = ts[n][kp*2], b2 = ts[n][kp*2+1];
        uint32_t ha,la,hb,lb;
        bsplit(a,ha,la); bsplit(b2,hb,lb);
        size_t o = (size_t)(rowbase+n)*(DM/2) + (kt0>>1) + kp;
        wh[o] = ha | (hb<<16);
        wl[o] = la | (lb<<16);
    }
}

// ===========================================================================
// HMMA GEMM core: 128(M)x64(N) tile, K=256 in 4 chunks, 3-term split bf16.
// 256 threads = 8 warps x 16 rows. Accum o[8][4] per warp.
// SMEM: AH 0 (16K) AL 16K WH 32K (8K) WL 40K (8K) = 48K dynamic.
// ===========================================================================
#define GAH 0
#define GAL 16384
#define GWH 32768
#define GWL 40960
#define GEMM_SMEM 49152

__device__ __forceinline__ void gemm_mma_core(
    char* smem, uint32_t sb,
    const char* gah, const char* gal, int row0, int wrow, float (&o)[8][4])
{
    const int tid = threadIdx.x, lane = tid&31, wid = tid>>5;
    const char* gwh = (const char*)g_Wh;
    const char* gwl = (const char*)g_Wl;
    const uint32_t lrow = (uint32_t)(lane&15)*128 + (uint32_t)(lane&16);
    const uint32_t abase = sb + (uint32_t)(wid<<4)*128;

    #pragma unroll 1
    for (int kt = 0; kt < 4; kt++) {
        if (kt) __syncthreads();
        #pragma unroll
        for (int i=0;i<8;i++){
            int idx = tid + (i<<8);
            int arr = idx>>10, c = idx&1023, row = c>>3, j = c&7;
            const char* s = (arr?gal:gah) + (size_t)(row0+row)*512 + kt*128 + j*16;
            *(uint4*)(smem + (arr?GAL:GAH) + swz(row*128 + j*16)) = *(const uint4*)s;
        }
        #pragma unroll
        for (int i=0;i<4;i++){
            int idx = tid + (i<<8);
            int arr = idx>>9, c = idx&511, row = c>>3, j = c&7;
            const char* s = (arr?gwl:gwh) + (size_t)(wrow+row)*512 + kt*128 + j*16;
            *(uint4*)(smem + (arr?GWL:GWH) + swz(row*128 + j*16)) = *(const uint4*)s;
        }
        __syncthreads();

        #pragma unroll
        for (int c=0;c<4;c++){
            uint32_t ah[4], al[4];
            ldsm4(ah[0],ah[1],ah[2],ah[3], abase + GAH + swz(lrow + c*32));
            ldsm4(al[0],al[1],al[2],al[3], abase + GAL + swz(lrow + c*32));
            #pragma unroll
            for (int p=0;p<4;p++){
                uint32_t wh0,wh1,wh2,wh3, wl0,wl1,wl2,wl3;
                uint32_t boff = swz((uint32_t)(p<<11) + lrow + c*32);
                ldsm4(wh0,wh1,wh2,wh3, sb + GWH + boff);
                ldsm4(wl0,wl1,wl2,wl3, sb + GWL + boff);
                mma_bf16(o[2*p],   ah, wh0, wh2);
                mma_bf16(o[2*p+1], ah, wh1, wh3);
                mma_bf16(o[2*p],   ah, wl0, wl2);
                mma_bf16(o[2*p+1], ah, wl1, wl3);
                mma_bf16(o[2*p],   al, wh0, wh2);
                mma_bf16(o[2*p+1], al, wh1, wh3);
            }
        }
    }
}

// QKV projection -> split bf16 Q/K (Q pre-scaled by log2e/16), fp32 V
__global__ __launch_bounds__(256)
void gemm_qkv(const float* __restrict__ bq, const float* __restrict__ bk,
              const float* __restrict__ bv)
{
    extern __shared__ __align__(128) char smem[];
    const uint32_t sb = (uint32_t)__cvta_generic_to_shared(smem);
    const int tid = threadIdx.x, lane = tid&31, wid = tid>>5;
    const int row0 = blockIdx.x<<7;
    const int yy = blockIdx.y, mat = yy>>2, h = yy&3;
    const int col0 = h<<6;
    const float* bias = (mat==0)?bq:(mat==1)?bk:bv;
    const int wrow = mat*DM + col0;

    float o[8][4];
    #pragma unroll
    for (int j=0;j<8;j++){ o[j][0]=0.f;o[j][1]=0.f;o[j][2]=0.f;o[j][3]=0.f; }

    gemm_mma_core(smem, sb, (const char*)g_xh, (const char*)g_xl, row0, wrow, o);

    const int r = row0 + (wid<<4) + (lane>>2);
    const int b = r>>11, l = r&2047;
    const int bh = b*NH + h;
    const float scl = (mat==0) ? 0.09016844f : 1.0f;   // log2e/16 for Q

    if (mat < 2) {
        uint32_t* dh = (uint32_t*)((mat==0)?g_Qh:g_Kh);
        uint32_t* dl = (uint32_t*)((mat==0)?g_Ql:g_Kl);
        #pragma unroll
        for (int j=0;j<8;j++){
            int dcol = 8*j + ((lane&3)<<1);
            float2 bb = *(const float2*)&bias[col0 + dcol];
            float v0 = (o[j][0]+bb.x)*scl, v1 = (o[j][1]+bb.y)*scl;
            float v2 = (o[j][2]+bb.x)*scl, v3 = (o[j][3]+bb.y)*scl;
            uint32_t h0,l0,h1,l1,h2,l2,h3,l3;
            bsplit(v0,h0,l0); bsplit(v1,h1,l1);
            bsplit(v2,h2,l2); bsplit(v3,h3,l3);
            size_t p0 = (((size_t)bh*LSEQ + l)*HDIM + dcol)>>1;
            size_t p1 = (((size_t)bh*LSEQ + l+8)*HDIM + dcol)>>1;
            dh[p0] = h0|(h1<<16);  dl[p0] = l0|(l1<<16);
            dh[p1] = h2|(h3<<16);  dl[p1] = l2|(l3<<16);
        }
    } else {
        float* dv = g_V + ((size_t)bh*LSEQ)*HDIM;
        #pragma unroll
        for (int j=0;j<8;j++){
            int dcol = 8*j + ((lane&3)<<1);
            float2 bb = *(const float2*)&bias[col0 + dcol];
            *(float2*)&dv[(size_t)l*HDIM + dcol]     = make_float2(o[j][0]+bb.x, o[j][1]+bb.y);
            *(float2*)&dv[(size_t)(l+8)*HDIM + dcol] = make_float2(o[j][2]+bb.x, o[j][3]+bb.y);
        }
    }
}

// Output projection: CTX(split bf16) @ Wo + bo -> d_out fp32
__global__ __launch_bounds__(256)
void gemm_out(const float* __restrict__ bo, float* __restrict__ C)
{
    extern __shared__ __align__(128) char smem[];
    const uint32_t sb = (uint32_t)__cvta_generic_to_shared(smem);
    const int tid = threadIdx.x, lane = tid&31, wid = tid>>5;
    const int row0 = blockIdx.x<<7;
    const int col0 = blockIdx.y<<6;
    const int wrow = 3*DM + col0;

    float o[8][4];
    #pragma unroll
    for (int j=0;j<8;j++){ o[j][0]=0.f;o[j][1]=0.f;o[j][2]=0.f;o[j][3]=0.f; }

    gemm_mma_core(smem, sb, (const char*)g_CXh, (const char*)g_CXl, row0, wrow, o);

    const int r = row0 + (wid<<4) + (lane>>2);
    #pragma unroll
    for (int j=0;j<8;j++){
        int dcol = 8*j + ((lane&3)<<1);
        float2 bb = *(const float2*)&bo[col0 + dcol];
        *(float2*)&C[(size_t)r*DOUT + col0 + dcol]     = make_float2(o[j][0]+bb.x, o[j][1]+bb.y);
        *(float2*)&C[(size_t)(r+8)*DOUT + col0 + dcol] = make_float2(o[j][2]+bb.x, o[j][3]+bb.y);
    }
}

// V transpose + split: g_V [bh][l][d] fp32 -> g_Vth/g_Vtl [bh][d][l] bf16
__global__ __launch_bounds__(256)
void vsplit_t()
{
    __shared__ float ts[64][65];
    const int tid = threadIdx.x;
    const int l0 = blockIdx.x<<6;
    const int bh = blockIdx.y;
    const float* src = g_V + ((size_t)bh*LSEQ + l0)*HDIM;
    #pragma unroll
    for (int i=0;i<16;i++){
        int e = tid + (i<<8);
        int r = e>>6, c = e&63;
        ts[c][r] = src[(size_t)r*HDIM + c];
    }
    __syncthreads();
    uint32_t* dh = (uint32_t*)g_Vth;
    uint32_t* dl = (uint32_t*)g_Vtl;
    #pragma unroll
    for (int i=0;i<8;i++){
        int f = tid + (i<<8);
        int d = f>>5, kp = f&31;
        float a = ts[d][kp*2], b2 = ts[d][kp*2+1];
        uint32_t ha,la,hb,lb;
        bsplit(a,ha,la); bsplit(b2,hb,lb);
        size_t o = ((size_t)bh*HDIM + d)*(LSEQ/2) + (l0>>1) + kp;
        dh[o] = ha | (hb<<16);
        dl[o] = la | (lb<<16);
    }
}

// ===========================================================================
// Warp-MMA flash attention (one-pass, no max subtraction; 3-term split bf16)
// Block = (bh, 128-query tile), 256 threads = 8 warps x 16 q-rows.
// ===========================================================================
#define SQH 0
#define SQL 16384
#define SKH 32768
#define SKL 40960
#define SVH 49152
#define SVL 57344
#define ATTN_SMEM 65536

__global__ __launch_bounds__(256,2)
void attn_mma()
{
    extern __shared__ __align__(128) char smem[];
    const uint32_t sb = (uint32_t)__cvta_generic_to_shared(smem);
    const int tid = threadIdx.x, lane = tid&31, wid = tid>>5;
    const int q0 = blockIdx.x<<7;
    const int bh = blockIdx.y;

    const char* gqh = (const char*)g_Qh;
    const char* gql = (const char*)g_Ql;
    const char* gkh = (const char*)g_Kh;
    const char* gkl = (const char*)g_Kl;
    const char* gvh = (const char*)g_Vth;
    const char* gvl = (const char*)g_Vtl;
    const size_t bhb = (size_t)bh*LSEQ*HDIM*2;

    #pragma unroll
    for (int i=0;i<8;i++){
        int idx = tid + (i<<8);
        int arr = idx>>10, c = idx&1023, row = c>>3, j = c&7;
        uint4 v = *(const uint4*)((arr?gql:gqh) + bhb + (size_t)(q0+row)*128 + j*16);
        *(uint4*)(smem + (arr?SQL:SQH) + swz(row*128 + j*16)) = v;
    }
    __syncthreads();

    const int qr0 = wid<<4;
    const uint32_t lrow = (uint32_t)(lane&15)*128 + (uint32_t)(lane&16);
    uint32_t qh[4][4];
    #pragma unroll
    for (int c=0;c<4;c++)
        ldsm4(qh[c][0],qh[c][1],qh[c][2],qh[c][3],
              sb + SQH + swz((uint32_t)qr0*128 + lrow + c*32));

    float o[8][4];
    #pragma unroll
    for (int j=0;j<8;j++){ o[j][0]=0.f;o[j][1]=0.f;o[j][2]=0.f;o[j][3]=0.f; }
    float lsum0 = 0.f, lsum1 = 0.f;

    #pragma unroll 1
    for (int kt = 0; kt < LSEQ/64; kt++) {
        const int k0 = kt<<6;
        __syncthreads();
        #pragma unroll
        for (int i=0;i<8;i++){
            int idx = tid + (i<<8);
            int arr = idx>>9, c = idx&511, row = c>>3, j = c&7;
            const char* s; uint32_t off;
            if      (arr==0){ s = gkh + bhb + (size_t)(k0+row)*128 + j*16; off = SKH; }
            else if (arr==1){ s = gkl + bhb + (size_t)(k0+row)*128 + j*16; off = SKL; }
            else if (arr==2){ s = gvh + bhb + (size_t)row*4096 + k0*2 + j*16; off = SVH; }
            else            { s = gvl + bhb + (size_t)row*4096 + k0*2 + j*16; off = SVL; }
            uint4 v = *(const uint4*)s;
            *(uint4*)(smem + off + swz(row*128 + j*16)) = v;
        }
        __syncthreads();

        float s[8][4];
        #pragma unroll
        for (int j=0;j<8;j++){ s[j][0]=0.f;s[j][1]=0.f;s[j][2]=0.f;s[j][3]=0.f; }
        #pragma unroll
        for (int c=0;c<4;c++){
            uint32_t ql[4];
            ldsm4(ql[0],ql[1],ql[2],ql[3], sb + SQL + swz((uint32_t)qr0*128 + lrow + c*32));
            #pragma unroll
            for (int p=0;p<4;p++){
                uint32_t kh0,kh1,kh2,kh3, kl0,kl1,kl2,kl3;
                uint32_t boff = swz((uint32_t)(p<<11) + lrow + c*32);
                ldsm4(kh0,kh1,kh2,kh3, sb + SKH + boff);
                ldsm4(kl0,kl1,kl2,kl3, sb + SKL + boff);
                mma_bf16(s[2*p],   qh[c], kh0, kh2);
                mma_bf16(s[2*p+1], qh[c], kh1, kh3);
                mma_bf16(s[2*p],   qh[c], kl0, kl2);
                mma_bf16(s[2*p+1], qh[c], kl1, kl3);
                mma_bf16(s[2*p],   ql,    kh0, kh2);
                mma_bf16(s[2*p+1], ql,    kh1, kh3);
            }
        }

        uint32_t ph[4][4], pl[4][4];
        #pragma unroll
        for (int j=0;j<8;j++){
            float p0 = ex2f(s[j][0]), p1 = ex2f(s[j][1]);
            float p2 = ex2f(s[j][2]), p3 = ex2f(s[j][3]);
            lsum0 += p0 + p1;  lsum1 += p2 + p3;
            uint32_t u0=__float_as_uint(p0), u1=__float_as_uint(p1);
            uint32_t u2=__float_as_uint(p2), u3=__float_as_uint(p3);
            int c = j>>1, r = (j&1)<<1;
            ph[c][r+0] = prmt_hi(u0,u1);
            ph[c][r+1] = prmt_hi(u2,u3);
            pl[c][r+0] = cvt2(p0 - __uint_as_float(u0&0xffff0000u),
                              p1 - __uint_as_float(u1&0xffff0000u));
            pl[c][r+1] = cvt2(p2 - __uint_as_float(u2&0xffff0000u),
                              p3 - __uint_as_float(u3&0xffff0000u));
        }

        #pragma unroll
        for (int c=0;c<4;c++){
            #pragma unroll
            for (int p=0;p<4;p++){
                uint32_t vh0,vh1,vh2,vh3, vl0,vl1,vl2,vl3;
                uint32_t boff = swz((uint32_t)(p<<11) + lrow + c*32);
                ldsm4(vh0,vh1,vh2,vh3, sb + SVH + boff);
                ldsm4(vl0,vl1,vl2,vl3, sb + SVL + boff);
                mma_bf16(o[2*p],   ph[c], vh0, vh2);
                mma_bf16(o[2*p+1], ph[c], vh1, vh3);
                mma_bf16(o[2*p],   ph[c], vl0, vl2);
                mma_bf16(o[2*p+1], ph[c], vl1, vl3);
                mma_bf16(o[2*p],   pl[c], vh0, vh2);
                mma_bf16(o[2*p+1], pl[c], vh1, vh3);
            }
        }
    }

    lsum0 += __shfl_xor_sync(0xffffffffu, lsum0, 1);
    lsum0 += __shfl_xor_sync(0xffffffffu, lsum0, 2);
    lsum1 += __shfl_xor_sync(0xffffffffu, lsum1, 1);
    lsum1 += __shfl_xor_sync(0xffffffffu, lsum1, 2);
    const float inv0 = 1.0f/lsum0, inv1 = 1.0f/lsum1;

    // write ctx split-bf16 [b,l, h*64+c]
    const int b = bh>>2, h = bh&3;
    const int r0 = q0 + qr0 + (lane>>2);
    uint32_t* ch = (uint32_t*)g_CXh;
    uint32_t* cl = (uint32_t*)g_CXl;
    #pragma unroll
    for (int j=0;j<8;j++){
        int dcol = 8*j + ((lane&3)<<1);
        float v0 = o[j][0]*inv0, v1 = o[j][1]*inv0;
        float v2 = o[j][2]*inv1, v3 = o[j][3]*inv1;
        uint32_t h0,l0,h1,l1,h2,l2,h3,l3;
        bsplit(v0,h0,l0); bsplit(v1,h1,l1);
        bsplit(v2,h2,l2); bsplit(v3,h3,l3);
        size_t p0 = (((size_t)(b*LSEQ + r0))*DM + h*HDIM + dcol)>>1;
        size_t p1 = (((size_t)(b*LSEQ + r0+8))*DM + h*HDIM + dcol)>>1;
        ch[p0] = h0|(h1<<16);  cl[p0] = l0|(l1<<16);
        ch[p1] = h2|(h3<<16);  cl[p1] = l2|(l3<<16);
    }
}

// ---------------------------------------------------------------------------
extern "C" void kernel_launch(void* const* d_in, const int* in_sizes, int n_in,
                              void* d_out, int out_size)
{
    const float* x  = (const float*)d_in[0];
    const float* Wq = (const float*)d_in[1];
    const float* bq = (const float*)d_in[2];
    const float* Wk = (const float*)d_in[3];
    const float* bk = (const float*)d_in[4];
    const float* Wv = (const float*)d_in[5];
    const float* bv = (const float*)d_in[6];
    const float* Wo = (const float*)d_in[7];
    const float* bo = (const float*)d_in[8];
    float* out = (float*)d_out;

    xsplit<<<2048, 256>>>(x);
    wsplit<<<112, 256>>>(Wq, Wk, Wv, Wo);

    cudaFuncSetAttribute(gemm_qkv, cudaFuncAttributeMaxDynamicSharedMemorySize, GEMM_SMEM);
    gemm_qkv<<<dim3(NTOK/128, 12), 256, GEMM_SMEM>>>(bq, bk, bv);
    vsplit_t<<<dim3(LSEQ/64, NBH), 256>>>();

    cudaFuncSetAttribute(attn_mma, cudaFuncAttributeMaxDynamicSharedMemorySize, ATTN_SMEM);
    attn_mma<<<dim3(LSEQ/128, NBH), 256, ATTN_SMEM>>>();

    cudaFuncSetAttribute(gemm_out, cudaFuncAttributeMaxDynamicSharedMemorySize, GEMM_SMEM);
    gemm_out<<<dim3(NTOK/128, DOUT/64), 256, GEMM_SMEM>>>(bo, out);
}

// round 7
// speedup vs baseline: 2.9379x; 1.0928x over previous
#include <cuda_runtime.h>
#include <stdint.h>

typedef unsigned long long u64;

#define LSEQ 2048
#define BATCH 8
#define NH 4
#define NBH (BATCH*NH)      // 32
#define HDIM 64
#define DM 256
#define DOUT 1024
#define NTOK (BATCH*LSEQ)   // 16384

// ---------------- device scratch (no runtime alloc allowed) ----------------
__device__ __align__(16) unsigned short g_Qh[(size_t)NBH*LSEQ*HDIM];  // bf16, pre-scaled by log2e/16
__device__ __align__(16) unsigned short g_Ql[(size_t)NBH*LSEQ*HDIM];
__device__ __align__(16) unsigned short g_Kh[(size_t)NBH*LSEQ*HDIM];
__device__ __align__(16) unsigned short g_Kl[(size_t)NBH*LSEQ*HDIM];
__device__ __align__(16) float          g_V [(size_t)NBH*LSEQ*HDIM];  // fp32 [bh][l][d]
__device__ __align__(16) unsigned short g_Vth[(size_t)NBH*HDIM*LSEQ]; // bf16 [bh][d][l]
__device__ __align__(16) unsigned short g_Vtl[(size_t)NBH*HDIM*LSEQ];
__device__ __align__(16) unsigned short g_xh[(size_t)NTOK*DM];        // split x
__device__ __align__(16) unsigned short g_xl[(size_t)NTOK*DM];
__device__ __align__(16) unsigned short g_CXh[(size_t)NTOK*DM];       // split ctx [b,l,h*64+j]
__device__ __align__(16) unsigned short g_CXl[(size_t)NTOK*DM];
#define WROWS (3*DM + DOUT)   // 1792 rows of W^T (qkv then out)
__device__ __align__(16) unsigned short g_Wh[(size_t)WROWS*DM];       // W^T split [n][k]
__device__ __align__(16) unsigned short g_Wl[(size_t)WROWS*DM];

// ---------------- scalar helpers ----------------
__device__ __forceinline__ void bsplit(float x, uint32_t &h16, uint32_t &l16){
    uint32_t u = __float_as_uint(x);
    uint32_t rh = u + 0x7fffu + ((u>>16)&1u);
    h16 = rh >> 16;
    float xl = x - __uint_as_float(rh & 0xffff0000u);
    uint32_t v = __float_as_uint(xl);
    l16 = (v + 0x7fffu + ((v>>16)&1u)) >> 16;
}
__device__ __forceinline__ float ex2f(float x){
    float r; asm("ex2.approx.f32 %0,%1;":"=f"(r):"f"(x)); return r; }
__device__ __forceinline__ uint32_t prmt_hi(uint32_t a, uint32_t b){
    uint32_t r; asm("prmt.b32 %0,%1,%2,0x7632;":"=r"(r):"r"(a),"r"(b)); return r; }
__device__ __forceinline__ uint32_t cvt2(float lo, float hi){
    uint32_t r; asm("cvt.rn.bf16x2.f32 %0,%1,%2;":"=r"(r):"f"(hi),"f"(lo)); return r; }

// ---------------- warp-MMA + cp.async primitives ----------------
__device__ __forceinline__ void ldsm4(uint32_t &r0, uint32_t &r1, uint32_t &r2, uint32_t &r3, uint32_t addr){
    asm volatile("ldmatrix.sync.aligned.m8n8.x4.shared.b16 {%0,%1,%2,%3},[%4];"
        : "=r"(r0),"=r"(r1),"=r"(r2),"=r"(r3) : "r"(addr));
}
__device__ __forceinline__ void mma_bf16(float* d, const uint32_t* a, uint32_t b0, uint32_t b1){
    asm volatile("mma.sync.aligned.m16n8k16.row.col.f32.bf16.bf16.f32 "
        "{%0,%1,%2,%3},{%4,%5,%6,%7},{%8,%9},{%0,%1,%2,%3};"
        : "+f"(d[0]),"+f"(d[1]),"+f"(d[2]),"+f"(d[3])
        : "r"(a[0]),"r"(a[1]),"r"(a[2]),"r"(a[3]),"r"(b0),"r"(b1));
}
__device__ __forceinline__ uint32_t swz(uint32_t o){ return o ^ ((o>>3)&0x70u); }
__device__ __forceinline__ void cpa16(uint32_t saddr, const void* g){
    asm volatile("cp.async.cg.shared.global [%0],[%1],16;"::"r"(saddr),"l"(g));
}
#define CPCOMMIT() asm volatile("cp.async.commit_group;":::"memory")
template<int N> __device__ __forceinline__ void cpwait(){
    asm volatile("cp.async.wait_group %0;"::"n"(N):"memory");
}

// ===========================================================================
// Prep kernels
// ===========================================================================
__global__ __launch_bounds__(256)
void xsplit(const float* __restrict__ x)
{
    uint32_t* xh = (uint32_t*)g_xh;
    uint32_t* xl = (uint32_t*)g_xl;
    size_t p0 = (size_t)blockIdx.x*1024 + threadIdx.x;
    #pragma unroll
    for (int i=0;i<4;i++){
        size_t p = p0 + (size_t)i*256;
        float2 v = ((const float2*)x)[p];
        uint32_t ha,la,hb,lb;
        bsplit(v.x,ha,la); bsplit(v.y,hb,lb);
        xh[p] = ha | (hb<<16);
        xl[p] = la | (lb<<16);
    }
}

__global__ __launch_bounds__(256)
void wsplit(const float* __restrict__ Wq, const float* __restrict__ Wk,
            const float* __restrict__ Wv, const float* __restrict__ Wo)
{
    __shared__ float ts[64][65];
    const int tid = threadIdx.x;
    int bx = blockIdx.x;
    const float* W; int N, kt0, nt0, rowbase;
    if (bx < 48) {
        int mat = bx/16, t = bx%16;
        W = (mat==0)?Wq:(mat==1)?Wk:Wv; N = DM;
        kt0 = (t>>2)<<6; nt0 = (t&3)<<6; rowbase = mat*DM + nt0;
    } else {
        bx -= 48;
        W = Wo; N = DOUT;
        kt0 = (bx&3)<<6; nt0 = (bx>>2)<<6; rowbase = 3*DM + nt0;
    }
    #pragma unroll
    for (int i=0;i<16;i++){
        int e = tid + (i<<8);
        int k = e>>6, n = e&63;
        ts[n][k] = W[(size_t)(kt0+k)*N + nt0 + n];
    }
    __syncthreads();
    uint32_t* wh = (uint32_t*)g_Wh;
    uint32_t* wl = (uint32_t*)g_Wl;
    #pragma unroll
    for (int i=0;i<8;i++){
        int e = tid + (i<<8);
        int n = e>>5, kp = e&31;
        float a = ts[n][kp*2], b2 = ts[n][kp*2+1];
        uint32_t ha,la,hb,lb;
        bsplit(a,ha,la); bsplit(b2,hb,lb);
        size_t o = (size_t)(rowbase+n)*(DM/2) + (kt0>>1) + kp;
        wh[o] = ha | (hb<<16);
        wl[o] = la | (lb<<16);
    }
}

// ===========================================================================
// HMMA GEMM core, cp.async double-buffered.
// 128(M)x64(N) tile, K=256 in 4 chunks, 3-term split bf16.
// Buffer layout (48KB each): AH 0, AL 16K, WH 32K, WL 40K. Two buffers.
// ===========================================================================
#define GAH 0
#define GAL 16384
#define GWH 32768
#define GWL 40960
#define GBUF 49152
#define GEMM_SMEM 98304

__device__ __forceinline__ void gemm_stage(
    uint32_t sb, uint32_t buf,
    const char* gah, const char* gal, int row0, int wrow, int kt)
{
    const int tid = threadIdx.x;
    const char* gwh = (const char*)g_Wh;
    const char* gwl = (const char*)g_Wl;
    #pragma unroll
    for (int i=0;i<8;i++){
        int idx = tid + (i<<8);
        int arr = idx>>10, c = idx&1023, row = c>>3, j = c&7;
        const char* s = (arr?gal:gah) + (size_t)(row0+row)*512 + kt*128 + j*16;
        cpa16(sb + buf + (arr?GAL:GAH) + swz(row*128 + j*16), s);
    }
    #pragma unroll
    for (int i=0;i<4;i++){
        int idx = tid + (i<<8);
        int arr = idx>>9, c = idx&511, row = c>>3, j = c&7;
        const char* s = (arr?gwl:gwh) + (size_t)(wrow+row)*512 + kt*128 + j*16;
        cpa16(sb + buf + (arr?GWL:GWH) + swz(row*128 + j*16), s);
    }
}

__device__ __forceinline__ void gemm_mma_core(
    uint32_t sb, const char* gah, const char* gal, int row0, int wrow, float (&o)[8][4])
{
    const int tid = threadIdx.x, lane = tid&31, wid = tid>>5;
    const uint32_t lrow = (uint32_t)(lane&15)*128 + (uint32_t)(lane&16);

    gemm_stage(sb, 0, gah, gal, row0, wrow, 0);
    CPCOMMIT();

    #pragma unroll 1
    for (int kt = 0; kt < 4; kt++) {
        const uint32_t buf = (kt&1) ? GBUF : 0;
        if (kt < 3) {
            gemm_stage(sb, (kt&1)?0:GBUF, gah, gal, row0, wrow, kt+1);
            CPCOMMIT();
            cpwait<1>();
        } else {
            cpwait<0>();
        }
        __syncthreads();

        const uint32_t abase = sb + buf + (uint32_t)(wid<<4)*128;
        #pragma unroll
        for (int c=0;c<4;c++){
            uint32_t ah[4], al[4];
            ldsm4(ah[0],ah[1],ah[2],ah[3], abase + GAH + swz(lrow + c*32));
            ldsm4(al[0],al[1],al[2],al[3], abase + GAL + swz(lrow + c*32));
            #pragma unroll
            for (int p=0;p<4;p++){
                uint32_t wh0,wh1,wh2,wh3, wl0,wl1,wl2,wl3;
                uint32_t boff = swz((uint32_t)(p<<11) + lrow + c*32);
                ldsm4(wh0,wh1,wh2,wh3, sb + buf + GWH + boff);
                ldsm4(wl0,wl1,wl2,wl3, sb + buf + GWL + boff);
                mma_bf16(o[2*p],   ah, wh0, wh2);
                mma_bf16(o[2*p+1], ah, wh1, wh3);
                mma_bf16(o[2*p],   ah, wl0, wl2);
                mma_bf16(o[2*p+1], ah, wl1, wl3);
                mma_bf16(o[2*p],   al, wh0, wh2);
                mma_bf16(o[2*p+1], al, wh1, wh3);
            }
        }
        __syncthreads();
    }
}

// QKV projection -> split bf16 Q/K (Q pre-scaled by log2e/16), fp32 V
__global__ __launch_bounds__(256,2)
void gemm_qkv(const float* __restrict__ bq, const float* __restrict__ bk,
              const float* __restrict__ bv)
{
    extern __shared__ __align__(128) char smem[];
    const uint32_t sb = (uint32_t)__cvta_generic_to_shared(smem);
    const int tid = threadIdx.x, lane = tid&31, wid = tid>>5;
    const int row0 = blockIdx.x<<7;
    const int yy = blockIdx.y, mat = yy>>2, h = yy&3;
    const int col0 = h<<6;
    const float* bias = (mat==0)?bq:(mat==1)?bk:bv;
    const int wrow = mat*DM + col0;

    float o[8][4];
    #pragma unroll
    for (int j=0;j<8;j++){ o[j][0]=0.f;o[j][1]=0.f;o[j][2]=0.f;o[j][3]=0.f; }

    gemm_mma_core(sb, (const char*)g_xh, (const char*)g_xl, row0, wrow, o);

    const int r = row0 + (wid<<4) + (lane>>2);
    const int b = r>>11, l = r&2047;
    const int bh = b*NH + h;
    const float scl = (mat==0) ? 0.09016844f : 1.0f;   // log2e/16 for Q

    if (mat < 2) {
        uint32_t* dh = (uint32_t*)((mat==0)?g_Qh:g_Kh);
        uint32_t* dl = (uint32_t*)((mat==0)?g_Ql:g_Kl);
        #pragma unroll
        for (int j=0;j<8;j++){
            int dcol = 8*j + ((lane&3)<<1);
            float2 bb = *(const float2*)&bias[col0 + dcol];
            float v0 = (o[j][0]+bb.x)*scl, v1 = (o[j][1]+bb.y)*scl;
            float v2 = (o[j][2]+bb.x)*scl, v3 = (o[j][3]+bb.y)*scl;
            uint32_t h0,l0,h1,l1,h2,l2,h3,l3;
            bsplit(v0,h0,l0); bsplit(v1,h1,l1);
            bsplit(v2,h2,l2); bsplit(v3,h3,l3);
            size_t p0 = (((size_t)bh*LSEQ + l)*HDIM + dcol)>>1;
            size_t p1 = (((size_t)bh*LSEQ + l+8)*HDIM + dcol)>>1;
            dh[p0] = h0|(h1<<16);  dl[p0] = l0|(l1<<16);
            dh[p1] = h2|(h3<<16);  dl[p1] = l2|(l3<<16);
        }
    } else {
        float* dv = g_V + ((size_t)bh*LSEQ)*HDIM;
        #pragma unroll
        for (int j=0;j<8;j++){
            int dcol = 8*j + ((lane&3)<<1);
            float2 bb = *(const float2*)&bias[col0 + dcol];
            *(float2*)&dv[(size_t)l*HDIM + dcol]     = make_float2(o[j][0]+bb.x, o[j][1]+bb.y);
            *(float2*)&dv[(size_t)(l+8)*HDIM + dcol] = make_float2(o[j][2]+bb.x, o[j][3]+bb.y);
        }
    }
}

// Output projection: CTX(split bf16) @ Wo + bo -> d_out fp32
__global__ __launch_bounds__(256,2)
void gemm_out(const float* __restrict__ bo, float* __restrict__ C)
{
    extern __shared__ __align__(128) char smem[];
    const uint32_t sb = (uint32_t)__cvta_generic_to_shared(smem);
    const int tid = threadIdx.x, lane = tid&31, wid = tid>>5;
    const int row0 = blockIdx.x<<7;
    const int col0 = blockIdx.y<<6;
    const int wrow = 3*DM + col0;

    float o[8][4];
    #pragma unroll
    for (int j=0;j<8;j++){ o[j][0]=0.f;o[j][1]=0.f;o[j][2]=0.f;o[j][3]=0.f; }

    gemm_mma_core(sb, (const char*)g_CXh, (const char*)g_CXl, row0, wrow, o);

    const int r = row0 + (wid<<4) + (lane>>2);
    #pragma unroll
    for (int j=0;j<8;j++){
        int dcol = 8*j + ((lane&3)<<1);
        float2 bb = *(const float2*)&bo[col0 + dcol];
        *(float2*)&C[(size_t)r*DOUT + col0 + dcol]     = make_float2(o[j][0]+bb.x, o[j][1]+bb.y);
        *(float2*)&C[(size_t)(r+8)*DOUT + col0 + dcol] = make_float2(o[j][2]+bb.x, o[j][3]+bb.y);
    }
}

// V transpose + split
__global__ __launch_bounds__(256)
void vsplit_t()
{
    __shared__ float ts[64][65];
    const int tid = threadIdx.x;
    const int l0 = blockIdx.x<<6;
    const int bh = blockIdx.y;
    const float* src = g_V + ((size_t)bh*LSEQ + l0)*HDIM;
    #pragma unroll
    for (int i=0;i<16;i++){
        int e = tid + (i<<8);
        int r = e>>6, c = e&63;
        ts[c][r] = src[(size_t)r*HDIM + c];
    }
    __syncthreads();
    uint32_t* dh = (uint32_t*)g_Vth;
    uint32_t* dl = (uint32_t*)g_Vtl;
    #pragma unroll
    for (int i=0;i<8;i++){
        int f = tid + (i<<8);
        int d = f>>5, kp = f&31;
        float a = ts[d][kp*2], b2 = ts[d][kp*2+1];
        uint32_t ha,la,hb,lb;
        bsplit(a,ha,la); bsplit(b2,hb,lb);
        size_t o = ((size_t)bh*HDIM + d)*(LSEQ/2) + (l0>>1) + kp;
        dh[o] = ha | (hb<<16);
        dl[o] = la | (lb<<16);
    }
}

// ===========================================================================
// Warp-MMA flash attention, cp.async double-buffered K/V.
// SMEM: QH 0 (16K) QL 16K | KV buf0 @32K (32K: KH,KL,VH,VL 8K each) | buf1 @64K
// ===========================================================================
#define SQH 0
#define SQL 16384
#define KVB 32768
#define KH_O 0
#define KL_O 8192
#define VH_O 16384
#define VL_O 24576
#define ATTN_SMEM 98304

__device__ __forceinline__ void attn_stage_kv(
    uint32_t sb, uint32_t buf, size_t bhb, int k0,
    const char* gkh, const char* gkl, const char* gvh, const char* gvl)
{
    const int tid = threadIdx.x;
    #pragma unroll
    for (int i=0;i<8;i++){
        int idx = tid + (i<<8);
        int arr = idx>>9, c = idx&511, row = c>>3, j = c&7;
        const char* s; uint32_t off;
        if      (arr==0){ s = gkh + bhb + (size_t)(k0+row)*128 + j*16; off = KH_O; }
        else if (arr==1){ s = gkl + bhb + (size_t)(k0+row)*128 + j*16; off = KL_O; }
        else if (arr==2){ s = gvh + bhb + (size_t)row*4096 + k0*2 + j*16; off = VH_O; }
        else            { s = gvl + bhb + (size_t)row*4096 + k0*2 + j*16; off = VL_O; }
        cpa16(sb + buf + off + swz(row*128 + j*16), s);
    }
}

__global__ __launch_bounds__(256,2)
void attn_mma()
{
    extern __shared__ __align__(128) char smem[];
    const uint32_t sb = (uint32_t)__cvta_generic_to_shared(smem);
    const int tid = threadIdx.x, lane = tid&31, wid = tid>>5;
    const int q0 = blockIdx.x<<7;
    const int bh = blockIdx.y;

    const char* gqh = (const char*)g_Qh;
    const char* gql = (const char*)g_Ql;
    const char* gkh = (const char*)g_Kh;
    const char* gkl = (const char*)g_Kl;
    const char* gvh = (const char*)g_Vth;
    const char* gvl = (const char*)g_Vtl;
    const size_t bhb = (size_t)bh*LSEQ*HDIM*2;

    // stage Q + tile0 via cp.async (one group)
    #pragma unroll
    for (int i=0;i<8;i++){
        int idx = tid + (i<<8);
        int arr = idx>>10, c = idx&1023, row = c>>3, j = c&7;
        const char* s = (arr?gql:gqh) + bhb + (size_t)(q0+row)*128 + j*16;
        cpa16(sb + (arr?SQL:SQH) + swz(row*128 + j*16), s);
    }
    attn_stage_kv(sb, KVB, bhb, 0, gkh, gkl, gvh, gvl);
    CPCOMMIT();
    cpwait<0>();
    __syncthreads();

    const int qr0 = wid<<4;
    const uint32_t lrow = (uint32_t)(lane&15)*128 + (uint32_t)(lane&16);
    uint32_t qh[4][4];
    #pragma unroll
    for (int c=0;c<4;c++)
        ldsm4(qh[c][0],qh[c][1],qh[c][2],qh[c][3],
              sb + SQH + swz((uint32_t)qr0*128 + lrow + c*32));

    float o[8][4];
    #pragma unroll
    for (int j=0;j<8;j++){ o[j][0]=0.f;o[j][1]=0.f;o[j][2]=0.f;o[j][3]=0.f; }
    float lsum0 = 0.f, lsum1 = 0.f;

    #pragma unroll 1
    for (int kt = 0; kt < LSEQ/64; kt++) {
        const uint32_t buf = KVB + ((uint32_t)(kt&1)<<15);
        if (kt < LSEQ/64 - 1) {
            attn_stage_kv(sb, KVB + ((uint32_t)((kt+1)&1)<<15), bhb, (kt+1)<<6,
                          gkh, gkl, gvh, gvl);
            CPCOMMIT();
        }
        if (kt > 0) {
            if (kt < LSEQ/64 - 1) cpwait<1>(); else cpwait<0>();
            __syncthreads();
        }

        // ---- S = Qh*Kh + Qh*Kl + Ql*Kh ----
        float s[8][4];
        #pragma unroll
        for (int j=0;j<8;j++){ s[j][0]=0.f;s[j][1]=0.f;s[j][2]=0.f;s[j][3]=0.f; }
        #pragma unroll
        for (int c=0;c<4;c++){
            uint32_t ql[4];
            ldsm4(ql[0],ql[1],ql[2],ql[3], sb + SQL + swz((uint32_t)qr0*128 + lrow + c*32));
            #pragma unroll
            for (int p=0;p<4;p++){
                uint32_t kh0,kh1,kh2,kh3, kl0,kl1,kl2,kl3;
                uint32_t boff = swz((uint32_t)(p<<11) + lrow + c*32);
                ldsm4(kh0,kh1,kh2,kh3, sb + buf + KH_O + boff);
                ldsm4(kl0,kl1,kl2,kl3, sb + buf + KL_O + boff);
                mma_bf16(s[2*p],   qh[c], kh0, kh2);
                mma_bf16(s[2*p+1], qh[c], kh1, kh3);
                mma_bf16(s[2*p],   qh[c], kl0, kl2);
                mma_bf16(s[2*p+1], qh[c], kl1, kl3);
                mma_bf16(s[2*p],   ql,    kh0, kh2);
                mma_bf16(s[2*p+1], ql,    kh1, kh3);
            }
        }

        // ---- epilogue: exp2, rowsum, split into P A-fragments ----
        uint32_t ph[4][4], pl[4][4];
        #pragma unroll
        for (int j=0;j<8;j++){
            float p0 = ex2f(s[j][0]), p1 = ex2f(s[j][1]);
            float p2 = ex2f(s[j][2]), p3 = ex2f(s[j][3]);
            lsum0 += p0 + p1;  lsum1 += p2 + p3;
            uint32_t u0=__float_as_uint(p0), u1=__float_as_uint(p1);
            uint32_t u2=__float_as_uint(p2), u3=__float_as_uint(p3);
            int c = j>>1, r = (j&1)<<1;
            ph[c][r+0] = prmt_hi(u0,u1);
            ph[c][r+1] = prmt_hi(u2,u3);
            pl[c][r+0] = cvt2(p0 - __uint_as_float(u0&0xffff0000u),
                              p1 - __uint_as_float(u1&0xffff0000u));
            pl[c][r+1] = cvt2(p2 - __uint_as_float(u2&0xffff0000u),
                              p3 - __uint_as_float(u3&0xffff0000u));
        }

        // ---- O += Ph*Vh + Ph*Vl + Pl*Vh ----
        #pragma unroll
        for (int c=0;c<4;c++){
            #pragma unroll
            for (int p=0;p<4;p++){
                uint32_t vh0,vh1,vh2,vh3, vl0,vl1,vl2,vl3;
                uint32_t boff = swz((uint32_t)(p<<11) + lrow + c*32);
                ldsm4(vh0,vh1,vh2,vh3, sb + buf + VH_O + boff);
                ldsm4(vl0,vl1,vl2,vl3, sb + buf + VL_O + boff);
                mma_bf16(o[2*p],   ph[c], vh0, vh2);
                mma_bf16(o[2*p+1], ph[c], vh1, vh3);
                mma_bf16(o[2*p],   ph[c], vl0, vl2);
                mma_bf16(o[2*p+1], ph[c], vl1, vl3);
                mma_bf16(o[2*p],   pl[c], vh0, vh2);
                mma_bf16(o[2*p+1], pl[c], vh1, vh3);
            }
        }
        __syncthreads();   // all reads of buf done before it is refilled at kt+2
    }

    lsum0 += __shfl_xor_sync(0xffffffffu, lsum0, 1);
    lsum0 += __shfl_xor_sync(0xffffffffu, lsum0, 2);
    lsum1 += __shfl_xor_sync(0xffffffffu, lsum1, 1);
    lsum1 += __shfl_xor_sync(0xffffffffu, lsum1, 2);
    const float inv0 = 1.0f/lsum0, inv1 = 1.0f/lsum1;

    const int b = bh>>2, h = bh&3;
    const int r0 = q0 + qr0 + (lane>>2);
    uint32_t* ch = (uint32_t*)g_CXh;
    uint32_t* cl = (uint32_t*)g_CXl;
    #pragma unroll
    for (int j=0;j<8;j++){
        int dcol = 8*j + ((lane&3)<<1);
        float v0 = o[j][0]*inv0, v1 = o[j][1]*inv0;
        float v2 = o[j][2]*inv1, v3 = o[j][3]*inv1;
        uint32_t h0,l0,h1,l1,h2,l2,h3,l3;
        bsplit(v0,h0,l0); bsplit(v1,h1,l1);
        bsplit(v2,h2,l2); bsplit(v3,h3,l3);
        size_t p0 = (((size_t)(b*LSEQ + r0))*DM + h*HDIM + dcol)>>1;
        size_t p1 = (((size_t)(b*LSEQ + r0+8))*DM + h*HDIM + dcol)>>1;
        ch[p0] = h0|(h1<<16);  cl[p0] = l0|(l1<<16);
        ch[p1] = h2|(h3<<16);  cl[p1] = l2|(l3<<16);
    }
}

// ---------------------------------------------------------------------------
extern "C" void kernel_launch(void* const* d_in, const int* in_sizes, int n_in,
                              void* d_out, int out_size)
{
    const float* x  = (const float*)d_in[0];
    const float* Wq = (const float*)d_in[1];
    const float* bq = (const float*)d_in[2];
    const float* Wk = (const float*)d_in[3];
    const float* bk = (const float*)d_in[4];
    const float* Wv = (const float*)d_in[5];
    const float* bv = (const float*)d_in[6];
    const float* Wo = (const float*)d_in[7];
    const float* bo = (const float*)d_in[8];
    float* out = (float*)d_out;

    xsplit<<<2048, 256>>>(x);
    wsplit<<<112, 256>>>(Wq, Wk, Wv, Wo);

    cudaFuncSetAttribute(gemm_qkv, cudaFuncAttributeMaxDynamicSharedMemorySize, GEMM_SMEM);
    gemm_qkv<<<dim3(NTOK/128, 12), 256, GEMM_SMEM>>>(bq, bk, bv);
    vsplit_t<<<dim3(LSEQ/64, NBH), 256>>>();

    cudaFuncSetAttribute(attn_mma, cudaFuncAttributeMaxDynamicSharedMemorySize, ATTN_SMEM);
    attn_mma<<<dim3(LSEQ/128, NBH), 256, ATTN_SMEM>>>();

    cudaFuncSetAttribute(gemm_out, cudaFuncAttributeMaxDynamicSharedMemorySize, GEMM_SMEM);
    gemm_out<<<dim3(NTOK/128, DOUT/64), 256, GEMM_SMEM>>>(bo, out);
}

// round 8
// speedup vs baseline: 4.1431x; 1.4102x over previous
#include <cuda_runtime.h>
#include <cuda_fp16.h>
#include <stdint.h>

typedef unsigned long long u64;

#define LSEQ 2048
#define BATCH 8
#define NH 4
#define NBH (BATCH*NH)      // 32
#define HDIM 64
#define DM 256
#define DOUT 1024
#define NTOK (BATCH*LSEQ)   // 16384
#define SCALE 0.090168440055560214f   // log2(e)/16

// ---------------- device scratch (no runtime alloc allowed) ----------------
__device__ __align__(16) unsigned short g_Qh[(size_t)NBH*LSEQ*HDIM];  // fp16 split Q (unscaled)
__device__ __align__(16) unsigned short g_Ql[(size_t)NBH*LSEQ*HDIM];
__device__ __align__(16) unsigned short g_Kh[(size_t)NBH*LSEQ*HDIM];  // fp16 single K
__device__ __align__(16) float          g_V [(size_t)NBH*LSEQ*HDIM];  // fp32 [bh][l][d]
__device__ __align__(16) unsigned short g_Vth[(size_t)NBH*HDIM*LSEQ]; // fp16 single [bh][d][l]
__device__ __align__(16) unsigned short g_xh[(size_t)NTOK*DM];        // fp16 split x
__device__ __align__(16) unsigned short g_xl[(size_t)NTOK*DM];
__device__ __align__(16) unsigned short g_CXh[(size_t)NTOK*DM];       // fp16 split ctx
__device__ __align__(16) unsigned short g_CXl[(size_t)NTOK*DM];
#define WROWS (3*DM + DOUT)   // 1792 rows of W^T (qkv then out)
__device__ __align__(16) unsigned short g_Wh[(size_t)WROWS*DM];       // fp16 single W^T [n][k]

// ---------------- scalar helpers ----------------
__device__ __forceinline__ void hsplit(float x, uint32_t &h, uint32_t &l){
    __half hh = __float2half_rn(x);
    float r = x - __half2float(hh);
    __half ll = __float2half_rn(r);
    h = (uint32_t)__half_as_ushort(hh);
    l = (uint32_t)__half_as_ushort(ll);
}
__device__ __forceinline__ uint32_t hpack(float a, float b){
    __half2 h2 = __floats2half2_rn(a, b);
    return *(uint32_t*)&h2;
}
__device__ __forceinline__ void psplit2(float p0, float p1, uint32_t &hh, uint32_t &ll){
    __half2 h2 = __floats2half2_rn(p0, p1);
    float q0 = __half2float(__low2half(h2));
    float q1 = __half2float(__high2half(h2));
    __half2 l2 = __floats2half2_rn(p0 - q0, p1 - q1);
    hh = *(uint32_t*)&h2;
    ll = *(uint32_t*)&l2;
}
__device__ __forceinline__ float ex2f(float x){
    float r; asm("ex2.approx.f32 %0,%1;":"=f"(r):"f"(x)); return r; }

// ---------------- warp-MMA + cp.async primitives ----------------
__device__ __forceinline__ void ldsm4(uint32_t &r0, uint32_t &r1, uint32_t &r2, uint32_t &r3, uint32_t addr){
    asm volatile("ldmatrix.sync.aligned.m8n8.x4.shared.b16 {%0,%1,%2,%3},[%4];"
        : "=r"(r0),"=r"(r1),"=r"(r2),"=r"(r3) : "r"(addr));
}
__device__ __forceinline__ void mma_f16(float* d, const uint32_t* a, uint32_t b0, uint32_t b1){
    asm volatile("mma.sync.aligned.m16n8k16.row.col.f32.f16.f16.f32 "
        "{%0,%1,%2,%3},{%4,%5,%6,%7},{%8,%9},{%0,%1,%2,%3};"
        : "+f"(d[0]),"+f"(d[1]),"+f"(d[2]),"+f"(d[3])
        : "r"(a[0]),"r"(a[1]),"r"(a[2]),"r"(a[3]),"r"(b0),"r"(b1));
}
__device__ __forceinline__ uint32_t swz(uint32_t o){ return o ^ ((o>>3)&0x70u); }
__device__ __forceinline__ void cpa16(uint32_t saddr, const void* g){
    asm volatile("cp.async.cg.shared.global [%0],[%1],16;"::"r"(saddr),"l"(g));
}
#define CPCOMMIT() asm volatile("cp.async.commit_group;":::"memory")
template<int N> __device__ __forceinline__ void cpwait(){
    asm volatile("cp.async.wait_group %0;"::"n"(N):"memory");
}

// ===========================================================================
// Prep kernels
// ===========================================================================
__global__ __launch_bounds__(256)
void xsplit(const float* __restrict__ x)
{
    uint32_t* xh = (uint32_t*)g_xh;
    uint32_t* xl = (uint32_t*)g_xl;
    size_t p0 = (size_t)blockIdx.x*1024 + threadIdx.x;
    #pragma unroll
    for (int i=0;i<4;i++){
        size_t p = p0 + (size_t)i*256;
        float2 v = ((const float2*)x)[p];
        uint32_t ha,la,hb,lb;
        hsplit(v.x,ha,la); hsplit(v.y,hb,lb);
        xh[p] = ha | (hb<<16);
        xl[p] = la | (lb<<16);
    }
}

// W^T convert (single fp16). qkv (3 x 256x256) then Wo (256x1024) -> [n][k].
__global__ __launch_bounds__(256)
void wsplit(const float* __restrict__ Wq, const float* __restrict__ Wk,
            const float* __restrict__ Wv, const float* __restrict__ Wo)
{
    __shared__ float ts[64][65];
    const int tid = threadIdx.x;
    int bx = blockIdx.x;
    const float* W; int N, kt0, nt0, rowbase;
    if (bx < 48) {
        int mat = bx/16, t = bx%16;
        W = (mat==0)?Wq:(mat==1)?Wk:Wv; N = DM;
        kt0 = (t>>2)<<6; nt0 = (t&3)<<6; rowbase = mat*DM + nt0;
    } else {
        bx -= 48;
        W = Wo; N = DOUT;
        kt0 = (bx&3)<<6; nt0 = (bx>>2)<<6; rowbase = 3*DM + nt0;
    }
    #pragma unroll
    for (int i=0;i<16;i++){
        int e = tid + (i<<8);
        int k = e>>6, n = e&63;
        ts[n][k] = W[(size_t)(kt0+k)*N + nt0 + n];
    }
    __syncthreads();
    uint32_t* wh = (uint32_t*)g_Wh;
    #pragma unroll
    for (int i=0;i<8;i++){
        int e = tid + (i<<8);
        int n = e>>5, kp = e&31;
        size_t o = (size_t)(rowbase+n)*(DM/2) + (kt0>>1) + kp;
        wh[o] = hpack(ts[n][kp*2], ts[n][kp*2+1]);
    }
}

// ===========================================================================
// HMMA GEMM core: 128(M)x64(N) tile, K=256 in 4 chunks, fp16 2-term.
// Buffer (40KB): AH 0 (16K), AL 16K, WH 32K (8K). Double-buffered.
// ===========================================================================
#define GAH 0
#define GAL 16384
#define GWH 32768
#define GBUF 40960
#define GEMM_SMEM 81920

__device__ __forceinline__ void gemm_stage(
    uint32_t sb, uint32_t buf,
    const char* gah, const char* gal, int row0, int wrow, int kt)
{
    const int tid = threadIdx.x;
    const char* gwh = (const char*)g_Wh;
    #pragma unroll
    for (int i=0;i<8;i++){
        int idx = tid + (i<<8);
        int arr = idx>>10, c = idx&1023, row = c>>3, j = c&7;
        const char* s = (arr?gal:gah) + (size_t)(row0+row)*512 + kt*128 + j*16;
        cpa16(sb + buf + (arr?GAL:GAH) + swz(row*128 + j*16), s);
    }
    #pragma unroll
    for (int i=0;i<2;i++){
        int idx = tid + (i<<8);
        int row = idx>>3, j = idx&7;
        const char* s = gwh + (size_t)(wrow+row)*512 + kt*128 + j*16;
        cpa16(sb + buf + GWH + swz(row*128 + j*16), s);
    }
}

__device__ __forceinline__ void gemm_mma_core(
    uint32_t sb, const char* gah, const char* gal, int row0, int wrow, float (&o)[8][4])
{
    const int tid = threadIdx.x, lane = tid&31, wid = tid>>5;
    const uint32_t lrow = (uint32_t)(lane&15)*128 + (uint32_t)(lane&16);

    gemm_stage(sb, 0, gah, gal, row0, wrow, 0);
    CPCOMMIT();

    #pragma unroll 1
    for (int kt = 0; kt < 4; kt++) {
        const uint32_t buf = (kt&1) ? GBUF : 0;
        if (kt < 3) {
            gemm_stage(sb, (kt&1)?0:GBUF, gah, gal, row0, wrow, kt+1);
            CPCOMMIT();
            cpwait<1>();
        } else {
            cpwait<0>();
        }
        __syncthreads();

        const uint32_t abase = sb + buf + (uint32_t)(wid<<4)*128;
        #pragma unroll
        for (int c=0;c<4;c++){
            uint32_t ah[4], al[4];
            ldsm4(ah[0],ah[1],ah[2],ah[3], abase + GAH + swz(lrow + c*32));
            ldsm4(al[0],al[1],al[2],al[3], abase + GAL + swz(lrow + c*32));
            #pragma unroll
            for (int p=0;p<4;p++){
                uint32_t wh0,wh1,wh2,wh3;
                uint32_t boff = swz((uint32_t)(p<<11) + lrow + c*32);
                ldsm4(wh0,wh1,wh2,wh3, sb + buf + GWH + boff);
                mma_f16(o[2*p],   ah, wh0, wh2);
                mma_f16(o[2*p+1], ah, wh1, wh3);
                mma_f16(o[2*p],   al, wh0, wh2);
                mma_f16(o[2*p+1], al, wh1, wh3);
            }
        }
        __syncthreads();
    }
}

// QKV projection -> split fp16 Q (unscaled), single fp16 K, fp32 V
__global__ __launch_bounds__(256,2)
void gemm_qkv(const float* __restrict__ bq, const float* __restrict__ bk,
              const float* __restrict__ bv)
{
    extern __shared__ __align__(128) char smem[];
    const uint32_t sb = (uint32_t)__cvta_generic_to_shared(smem);
    const int tid = threadIdx.x, lane = tid&31, wid = tid>>5;
    const int row0 = blockIdx.x<<7;
    const int yy = blockIdx.y, mat = yy>>2, h = yy&3;
    const int col0 = h<<6;
    const float* bias = (mat==0)?bq:(mat==1)?bk:bv;
    const int wrow = mat*DM + col0;

    float o[8][4];
    #pragma unroll
    for (int j=0;j<8;j++){ o[j][0]=0.f;o[j][1]=0.f;o[j][2]=0.f;o[j][3]=0.f; }

    gemm_mma_core(sb, (const char*)g_xh, (const char*)g_xl, row0, wrow, o);

    const int r = row0 + (wid<<4) + (lane>>2);
    const int b = r>>11, l = r&2047;
    const int bh = b*NH + h;

    if (mat == 0) {
        uint32_t* dh = (uint32_t*)g_Qh;
        uint32_t* dl = (uint32_t*)g_Ql;
        #pragma unroll
        for (int j=0;j<8;j++){
            int dcol = 8*j + ((lane&3)<<1);
            float2 bb = *(const float2*)&bias[col0 + dcol];
            float v0 = o[j][0]+bb.x, v1 = o[j][1]+bb.y;
            float v2 = o[j][2]+bb.x, v3 = o[j][3]+bb.y;
            uint32_t h0,l0,h1,l1,h2,l2,h3,l3;
            hsplit(v0,h0,l0); hsplit(v1,h1,l1);
            hsplit(v2,h2,l2); hsplit(v3,h3,l3);
            size_t p0 = (((size_t)bh*LSEQ + l)*HDIM + dcol)>>1;
            size_t p1 = (((size_t)bh*LSEQ + l+8)*HDIM + dcol)>>1;
            dh[p0] = h0|(h1<<16);  dl[p0] = l0|(l1<<16);
            dh[p1] = h2|(h3<<16);  dl[p1] = l2|(l3<<16);
        }
    } else if (mat == 1) {
        uint32_t* dh = (uint32_t*)g_Kh;
        #pragma unroll
        for (int j=0;j<8;j++){
            int dcol = 8*j + ((lane&3)<<1);
            float2 bb = *(const float2*)&bias[col0 + dcol];
            size_t p0 = (((size_t)bh*LSEQ + l)*HDIM + dcol)>>1;
            size_t p1 = (((size_t)bh*LSEQ + l+8)*HDIM + dcol)>>1;
            dh[p0] = hpack(o[j][0]+bb.x, o[j][1]+bb.y);
            dh[p1] = hpack(o[j][2]+bb.x, o[j][3]+bb.y);
        }
    } else {
        float* dv = g_V + ((size_t)bh*LSEQ)*HDIM;
        #pragma unroll
        for (int j=0;j<8;j++){
            int dcol = 8*j + ((lane&3)<<1);
            float2 bb = *(const float2*)&bias[col0 + dcol];
            *(float2*)&dv[(size_t)l*HDIM + dcol]     = make_float2(o[j][0]+bb.x, o[j][1]+bb.y);
            *(float2*)&dv[(size_t)(l+8)*HDIM + dcol] = make_float2(o[j][2]+bb.x, o[j][3]+bb.y);
        }
    }
}

// Output projection: CTX(split fp16) @ Wo + bo -> d_out fp32
__global__ __launch_bounds__(256,2)
void gemm_out(const float* __restrict__ bo, float* __restrict__ C)
{
    extern __shared__ __align__(128) char smem[];
    const uint32_t sb = (uint32_t)__cvta_generic_to_shared(smem);
    const int tid = threadIdx.x, lane = tid&31, wid = tid>>5;
    const int row0 = blockIdx.x<<7;
    const int col0 = blockIdx.y<<6;
    const int wrow = 3*DM + col0;

    float o[8][4];
    #pragma unroll
    for (int j=0;j<8;j++){ o[j][0]=0.f;o[j][1]=0.f;o[j][2]=0.f;o[j][3]=0.f; }

    gemm_mma_core(sb, (const char*)g_CXh, (const char*)g_CXl, row0, wrow, o);

    const int r = row0 + (wid<<4) + (lane>>2);
    #pragma unroll
    for (int j=0;j<8;j++){
        int dcol = 8*j + ((lane&3)<<1);
        float2 bb = *(const float2*)&bo[col0 + dcol];
        *(float2*)&C[(size_t)r*DOUT + col0 + dcol]     = make_float2(o[j][0]+bb.x, o[j][1]+bb.y);
        *(float2*)&C[(size_t)(r+8)*DOUT + col0 + dcol] = make_float2(o[j][2]+bb.x, o[j][3]+bb.y);
    }
}

// V transpose + convert: g_V [bh][l][d] fp32 -> g_Vth [bh][d][l] fp16
__global__ __launch_bounds__(256)
void vsplit_t()
{
    __shared__ float ts[64][65];
    const int tid = threadIdx.x;
    const int l0 = blockIdx.x<<6;
    const int bh = blockIdx.y;
    const float* src = g_V + ((size_t)bh*LSEQ + l0)*HDIM;
    #pragma unroll
    for (int i=0;i<16;i++){
        int e = tid + (i<<8);
        int r = e>>6, c = e&63;
        ts[c][r] = src[(size_t)r*HDIM + c];
    }
    __syncthreads();
    uint32_t* dh = (uint32_t*)g_Vth;
    #pragma unroll
    for (int i=0;i<8;i++){
        int f = tid + (i<<8);
        int d = f>>5, kp = f&31;
        size_t o = ((size_t)bh*HDIM + d)*(LSEQ/2) + (l0>>1) + kp;
        dh[o] = hpack(ts[d][kp*2], ts[d][kp*2+1]);
    }
}

// ===========================================================================
// Warp-MMA flash attention, fp16 2-term, cp.async double-buffered K/V.
// SMEM: QH 0 (16K) QL 16K | KV buf0 @32K (KH 8K, VH 8K) | buf1 @48K = 64K
// ===========================================================================
#define SQH 0
#define SQL 16384
#define KVB 32768
#define KH_O 0
#define VH_O 8192
#define ATTN_SMEM 65536

__device__ __forceinline__ void attn_stage_kv(
    uint32_t sb, uint32_t buf, size_t bhb, int k0,
    const char* gkh, const char* gvh)
{
    const int tid = threadIdx.x;
    #pragma unroll
    for (int i=0;i<4;i++){
        int idx = tid + (i<<8);
        int arr = idx>>9, c = idx&511, row = c>>3, j = c&7;
        const char* s; uint32_t off;
        if (arr==0){ s = gkh + bhb + (size_t)(k0+row)*128 + j*16; off = KH_O; }
        else       { s = gvh + bhb + (size_t)row*4096 + k0*2 + j*16; off = VH_O; }
        cpa16(sb + buf + off + swz(row*128 + j*16), s);
    }
}

__global__ __launch_bounds__(256,2)
void attn_mma()
{
    extern __shared__ __align__(128) char smem[];
    const uint32_t sb = (uint32_t)__cvta_generic_to_shared(smem);
    const int tid = threadIdx.x, lane = tid&31, wid = tid>>5;
    const int q0 = blockIdx.x<<7;
    const int bh = blockIdx.y;

    const char* gqh = (const char*)g_Qh;
    const char* gql = (const char*)g_Ql;
    const char* gkh = (const char*)g_Kh;
    const char* gvh = (const char*)g_Vth;
    const size_t bhb = (size_t)bh*LSEQ*HDIM*2;

    // stage Q + tile0
    #pragma unroll
    for (int i=0;i<8;i++){
        int idx = tid + (i<<8);
        int arr = idx>>10, c = idx&1023, row = c>>3, j = c&7;
        const char* s = (arr?gql:gqh) + bhb + (size_t)(q0+row)*128 + j*16;
        cpa16(sb + (arr?SQL:SQH) + swz(row*128 + j*16), s);
    }
    attn_stage_kv(sb, KVB, bhb, 0, gkh, gvh);
    CPCOMMIT();
    cpwait<0>();
    __syncthreads();

    const int qr0 = wid<<4;
    const uint32_t lrow = (uint32_t)(lane&15)*128 + (uint32_t)(lane&16);
    uint32_t qh[4][4];
    #pragma unroll
    for (int c=0;c<4;c++)
        ldsm4(qh[c][0],qh[c][1],qh[c][2],qh[c][3],
              sb + SQH + swz((uint32_t)qr0*128 + lrow + c*32));

    float o[8][4];
    #pragma unroll
    for (int j=0;j<8;j++){ o[j][0]=0.f;o[j][1]=0.f;o[j][2]=0.f;o[j][3]=0.f; }
    float lsum0 = 0.f, lsum1 = 0.f;

    #pragma unroll 1
    for (int kt = 0; kt < LSEQ/64; kt++) {
        const uint32_t buf = KVB + ((uint32_t)(kt&1)<<14);
        if (kt < LSEQ/64 - 1) {
            attn_stage_kv(sb, KVB + ((uint32_t)((kt+1)&1)<<14), bhb, (kt+1)<<6, gkh, gvh);
            CPCOMMIT();
        }
        if (kt > 0) {
            if (kt < LSEQ/64 - 1) cpwait<1>(); else cpwait<0>();
            __syncthreads();
        }

        // ---- S = Qh*Kh + Ql*Kh (exact-Q x fp16-K) ----
        float s[8][4];
        #pragma unroll
        for (int j=0;j<8;j++){ s[j][0]=0.f;s[j][1]=0.f;s[j][2]=0.f;s[j][3]=0.f; }
        #pragma unroll
        for (int c=0;c<4;c++){
            uint32_t ql[4];
            ldsm4(ql[0],ql[1],ql[2],ql[3], sb + SQL + swz((uint32_t)qr0*128 + lrow + c*32));
            #pragma unroll
            for (int p=0;p<4;p++){
                uint32_t kh0,kh1,kh2,kh3;
                uint32_t boff = swz((uint32_t)(p<<11) + lrow + c*32);
                ldsm4(kh0,kh1,kh2,kh3, sb + buf + KH_O + boff);
                mma_f16(s[2*p],   qh[c], kh0, kh2);
                mma_f16(s[2*p+1], qh[c], kh1, kh3);
                mma_f16(s[2*p],   ql,    kh0, kh2);
                mma_f16(s[2*p+1], ql,    kh1, kh3);
            }
        }

        // ---- epilogue: exp2(scale*s), rowsum, split P into fp16 A-frags ----
        uint32_t ph[4][4], pl[4][4];
        #pragma unroll
        for (int j=0;j<8;j++){
            float p0 = ex2f(s[j][0]*SCALE), p1 = ex2f(s[j][1]*SCALE);
            float p2 = ex2f(s[j][2]*SCALE), p3 = ex2f(s[j][3]*SCALE);
            lsum0 += p0 + p1;  lsum1 += p2 + p3;
            int c = j>>1, r = (j&1)<<1;
            psplit2(p0, p1, ph[c][r+0], pl[c][r+0]);
            psplit2(p2, p3, ph[c][r+1], pl[c][r+1]);
        }

        // ---- O += Ph*Vh + Pl*Vh ----
        #pragma unroll
        for (int c=0;c<4;c++){
            #pragma unroll
            for (int p=0;p<4;p++){
                uint32_t vh0,vh1,vh2,vh3;
                uint32_t boff = swz((uint32_t)(p<<11) + lrow + c*32);
                ldsm4(vh0,vh1,vh2,vh3, sb + buf + VH_O + boff);
                mma_f16(o[2*p],   ph[c], vh0, vh2);
                mma_f16(o[2*p+1], ph[c], vh1, vh3);
                mma_f16(o[2*p],   pl[c], vh0, vh2);
                mma_f16(o[2*p+1], pl[c], vh1, vh3);
            }
        }
        __syncthreads();
    }

    lsum0 += __shfl_xor_sync(0xffffffffu, lsum0, 1);
    lsum0 += __shfl_xor_sync(0xffffffffu, lsum0, 2);
    lsum1 += __shfl_xor_sync(0xffffffffu, lsum1, 1);
    lsum1 += __shfl_xor_sync(0xffffffffu, lsum1, 2);
    const float inv0 = 1.0f/lsum0, inv1 = 1.0f/lsum1;

    const int b = bh>>2, h = bh&3;
    const int r0 = q0 + qr0 + (lane>>2);
    uint32_t* ch = (uint32_t*)g_CXh;
    uint32_t* cl = (uint32_t*)g_CXl;
    #pragma unroll
    for (int j=0;j<8;j++){
        int dcol = 8*j + ((lane&3)<<1);
        float v0 = o[j][0]*inv0, v1 = o[j][1]*inv0;
        float v2 = o[j][2]*inv1, v3 = o[j][3]*inv1;
        uint32_t h0,l0,h1,l1,h2,l2,h3,l3;
        hsplit(v0,h0,l0); hsplit(v1,h1,l1);
        hsplit(v2,h2,l2); hsplit(v3,h3,l3);
        size_t p0 = (((size_t)(b*LSEQ + r0))*DM + h*HDIM + dcol)>>1;
        size_t p1 = (((size_t)(b*LSEQ + r0+8))*DM + h*HDIM + dcol)>>1;
        ch[p0] = h0|(h1<<16);  cl[p0] = l0|(l1<<16);
        ch[p1] = h2|(h3<<16);  cl[p1] = l2|(l3<<16);
    }
}

// ---------------------------------------------------------------------------
extern "C" void kernel_launch(void* const* d_in, const int* in_sizes, int n_in,
                              void* d_out, int out_size)
{
    const float* x  = (const float*)d_in[0];
    const float* Wq = (const float*)d_in[1];
    const float* bq = (const float*)d_in[2];
    const float* Wk = (const float*)d_in[3];
    const float* bk = (const float*)d_in[4];
    const float* Wv = (const float*)d_in[5];
    const float* bv = (const float*)d_in[6];
    const float* Wo = (const float*)d_in[7];
    const float* bo = (const float*)d_in[8];
    float* out = (float*)d_out;

    xsplit<<<2048, 256>>>(x);
    wsplit<<<112, 256>>>(Wq, Wk, Wv, Wo);

    cudaFuncSetAttribute(gemm_qkv, cudaFuncAttributeMaxDynamicSharedMemorySize, GEMM_SMEM);
    gemm_qkv<<<dim3(NTOK/128, 12), 256, GEMM_SMEM>>>(bq, bk, bv);
    vsplit_t<<<dim3(LSEQ/64, NBH), 256>>>();

    cudaFuncSetAttribute(attn_mma, cudaFuncAttributeMaxDynamicSharedMemorySize, ATTN_SMEM);
    attn_mma<<<dim3(LSEQ/128, NBH), 256, ATTN_SMEM>>>();

    cudaFuncSetAttribute(gemm_out, cudaFuncAttributeMaxDynamicSharedMemorySize, GEMM_SMEM);
    gemm_out<<<dim3(NTOK/128, DOUT/64), 256, GEMM_SMEM>>>(bo, out);
}

// round 9
// speedup vs baseline: 4.9995x; 1.2067x over previous
#include <cuda_runtime.h>
#include <cuda_fp16.h>
#include <stdint.h>

typedef unsigned long long u64;

#define LSEQ 2048
#define BATCH 8
#define NH 4
#define NBH (BATCH*NH)      // 32
#define HDIM 64
#define DM 256
#define DOUT 1024
#define NTOK (BATCH*LSEQ)   // 16384
#define SCALE 0.090168440055560214f   // log2(e)/16

// ---------------- device scratch (no runtime alloc allowed) ----------------
__device__ __align__(16) unsigned short g_Qh[(size_t)NBH*LSEQ*HDIM];  // fp16 single Q (unscaled)
__device__ __align__(16) unsigned short g_Kh[(size_t)NBH*LSEQ*HDIM];  // fp16 single K
__device__ __align__(16) float          g_V [(size_t)NBH*LSEQ*HDIM];  // fp32 [bh][l][d]
__device__ __align__(16) unsigned short g_Vth[(size_t)NBH*HDIM*LSEQ]; // fp16 single [bh][d][l]
__device__ __align__(16) unsigned short g_xh[(size_t)NTOK*DM];        // fp16 single x
__device__ __align__(16) unsigned short g_CXh[(size_t)NTOK*DM];       // fp16 split ctx
__device__ __align__(16) unsigned short g_CXl[(size_t)NTOK*DM];
#define WROWS (3*DM + DOUT)   // 1792 rows of W^T (qkv then out)
__device__ __align__(16) unsigned short g_Wh[(size_t)WROWS*DM];       // fp16 single W^T [n][k]

// ---------------- scalar helpers ----------------
__device__ __forceinline__ void hsplit(float x, uint32_t &h, uint32_t &l){
    __half hh = __float2half_rn(x);
    float r = x - __half2float(hh);
    __half ll = __float2half_rn(r);
    h = (uint32_t)__half_as_ushort(hh);
    l = (uint32_t)__half_as_ushort(ll);
}
__device__ __forceinline__ uint32_t hpack(float a, float b){
    __half2 h2 = __floats2half2_rn(a, b);
    return *(uint32_t*)&h2;
}
__device__ __forceinline__ void psplit2(float p0, float p1, uint32_t &hh, uint32_t &ll){
    __half2 h2 = __floats2half2_rn(p0, p1);
    float q0 = __half2float(__low2half(h2));
    float q1 = __half2float(__high2half(h2));
    __half2 l2 = __floats2half2_rn(p0 - q0, p1 - q1);
    hh = *(uint32_t*)&h2;
    ll = *(uint32_t*)&l2;
}
__device__ __forceinline__ float ex2f(float x){
    float r; asm("ex2.approx.f32 %0,%1;":"=f"(r):"f"(x)); return r; }

// ---------------- warp-MMA + cp.async primitives ----------------
__device__ __forceinline__ void ldsm4(uint32_t &r0, uint32_t &r1, uint32_t &r2, uint32_t &r3, uint32_t addr){
    asm volatile("ldmatrix.sync.aligned.m8n8.x4.shared.b16 {%0,%1,%2,%3},[%4];"
        : "=r"(r0),"=r"(r1),"=r"(r2),"=r"(r3) : "r"(addr));
}
__device__ __forceinline__ void mma_f16(float* d, const uint32_t* a, uint32_t b0, uint32_t b1){
    asm volatile("mma.sync.aligned.m16n8k16.row.col.f32.f16.f16.f32 "
        "{%0,%1,%2,%3},{%4,%5,%6,%7},{%8,%9},{%0,%1,%2,%3};"
        : "+f"(d[0]),"+f"(d[1]),"+f"(d[2]),"+f"(d[3])
        : "r"(a[0]),"r"(a[1]),"r"(a[2]),"r"(a[3]),"r"(b0),"r"(b1));
}
__device__ __forceinline__ uint32_t swz(uint32_t o){ return o ^ ((o>>3)&0x70u); }
__device__ __forceinline__ void cpa16(uint32_t saddr, const void* g){
    asm volatile("cp.async.cg.shared.global [%0],[%1],16;"::"r"(saddr),"l"(g));
}
#define CPCOMMIT() asm volatile("cp.async.commit_group;":::"memory")
template<int N> __device__ __forceinline__ void cpwait(){
    asm volatile("cp.async.wait_group %0;"::"n"(N):"memory");
}

// ===========================================================================
// Prep kernels
// ===========================================================================
__global__ __launch_bounds__(256)
void xcvt(const float* __restrict__ x)
{
    uint32_t* xh = (uint32_t*)g_xh;
    size_t p0 = (size_t)blockIdx.x*1024 + threadIdx.x;
    #pragma unroll
    for (int i=0;i<4;i++){
        size_t p = p0 + (size_t)i*256;
        float2 v = ((const float2*)x)[p];
        xh[p] = hpack(v.x, v.y);
    }
}

// W^T convert (single fp16). qkv (3 x 256x256) then Wo (256x1024) -> [n][k].
__global__ __launch_bounds__(256)
void wsplit(const float* __restrict__ Wq, const float* __restrict__ Wk,
            const float* __restrict__ Wv, const float* __restrict__ Wo)
{
    __shared__ float ts[64][65];
    const int tid = threadIdx.x;
    int bx = blockIdx.x;
    const float* W; int N, kt0, nt0, rowbase;
    if (bx < 48) {
        int mat = bx/16, t = bx%16;
        W = (mat==0)?Wq:(mat==1)?Wk:Wv; N = DM;
        kt0 = (t>>2)<<6; nt0 = (t&3)<<6; rowbase = mat*DM + nt0;
    } else {
        bx -= 48;
        W = Wo; N = DOUT;
        kt0 = (bx&3)<<6; nt0 = (bx>>2)<<6; rowbase = 3*DM + nt0;
    }
    #pragma unroll
    for (int i=0;i<16;i++){
        int e = tid + (i<<8);
        int k = e>>6, n = e&63;
        ts[n][k] = W[(size_t)(kt0+k)*N + nt0 + n];
    }
    __syncthreads();
    uint32_t* wh = (uint32_t*)g_Wh;
    #pragma unroll
    for (int i=0;i<8;i++){
        int e = tid + (i<<8);
        int n = e>>5, kp = e&31;
        size_t o = (size_t)(rowbase+n)*(DM/2) + (kt0>>1) + kp;
        wh[o] = hpack(ts[n][kp*2], ts[n][kp*2+1]);
    }
}

// ===========================================================================
// HMMA GEMM core, templated on A-split. 128x64 tile, K=256 in 4 chunks.
// SPLITA buffer: AH 16K + AL 16K + WH 8K = 40K.  single: AH 16K + WH 8K = 24K.
// ===========================================================================
template<bool SPLITA> struct GOff {
    static constexpr uint32_t AH  = 0;
    static constexpr uint32_t AL  = 16384;
    static constexpr uint32_t WH  = SPLITA ? 32768u : 16384u;
    static constexpr uint32_t BUF = SPLITA ? 40960u : 24576u;
};
#define GEMM_SMEM_S 81920   // split-A: 2 x 40K
#define GEMM_SMEM_1 49152   // single-A: 2 x 24K

template<bool SPLITA>
__device__ __forceinline__ void gemm_stage(
    uint32_t sb, uint32_t buf,
    const char* gah, const char* gal, int row0, int wrow, int kt)
{
    const int tid = threadIdx.x;
    const char* gwh = (const char*)g_Wh;
    #pragma unroll
    for (int i=0;i<(SPLITA?8:4);i++){
        int idx = tid + (i<<8);
        int arr = SPLITA ? (idx>>10) : 0;
        int c = idx&1023, row = c>>3, j = c&7;
        const char* s = (arr?gal:gah) + (size_t)(row0+row)*512 + kt*128 + j*16;
        cpa16(sb + buf + (arr?GOff<SPLITA>::AL:GOff<SPLITA>::AH) + swz(row*128 + j*16), s);
    }
    #pragma unroll
    for (int i=0;i<2;i++){
        int idx = tid + (i<<8);
        int row = idx>>3, j = idx&7;
        const char* s = gwh + (size_t)(wrow+row)*512 + kt*128 + j*16;
        cpa16(sb + buf + GOff<SPLITA>::WH + swz(row*128 + j*16), s);
    }
}

template<bool SPLITA>
__device__ __forceinline__ void gemm_mma_core(
    uint32_t sb, const char* gah, const char* gal, int row0, int wrow, float (&o)[8][4])
{
    const int tid = threadIdx.x, lane = tid&31, wid = tid>>5;
    const uint32_t lrow = (uint32_t)(lane&15)*128 + (uint32_t)(lane&16);

    gemm_stage<SPLITA>(sb, 0, gah, gal, row0, wrow, 0);
    CPCOMMIT();

    #pragma unroll 1
    for (int kt = 0; kt < 4; kt++) {
        const uint32_t buf = (kt&1) ? GOff<SPLITA>::BUF : 0;
        if (kt < 3) {
            gemm_stage<SPLITA>(sb, (kt&1)?0:GOff<SPLITA>::BUF, gah, gal, row0, wrow, kt+1);
            CPCOMMIT();
            cpwait<1>();
        } else {
            cpwait<0>();
        }
        __syncthreads();

        const uint32_t abase = sb + buf + (uint32_t)(wid<<4)*128;
        #pragma unroll
        for (int c=0;c<4;c++){
            uint32_t ah[4], al[4];
            ldsm4(ah[0],ah[1],ah[2],ah[3], abase + GOff<SPLITA>::AH + swz(lrow + c*32));
            if (SPLITA)
                ldsm4(al[0],al[1],al[2],al[3], abase + GOff<SPLITA>::AL + swz(lrow + c*32));
            #pragma unroll
            for (int p=0;p<4;p++){
                uint32_t wh0,wh1,wh2,wh3;
                uint32_t boff = swz((uint32_t)(p<<11) + lrow + c*32);
                ldsm4(wh0,wh1,wh2,wh3, sb + buf + GOff<SPLITA>::WH + boff);
                mma_f16(o[2*p],   ah, wh0, wh2);
                mma_f16(o[2*p+1], ah, wh1, wh3);
                if (SPLITA){
                    mma_f16(o[2*p],   al, wh0, wh2);
                    mma_f16(o[2*p+1], al, wh1, wh3);
                }
            }
        }
        __syncthreads();
    }
}

// QKV projection (x single fp16): Q/K -> single fp16, V -> fp32
__global__ __launch_bounds__(256,2)
void gemm_qkv(const float* __restrict__ bq, const float* __restrict__ bk,
              const float* __restrict__ bv)
{
    extern __shared__ __align__(128) char smem[];
    const uint32_t sb = (uint32_t)__cvta_generic_to_shared(smem);
    const int tid = threadIdx.x, lane = tid&31, wid = tid>>5;
    const int row0 = blockIdx.x<<7;
    const int yy = blockIdx.y, mat = yy>>2, h = yy&3;
    const int col0 = h<<6;
    const float* bias = (mat==0)?bq:(mat==1)?bk:bv;
    const int wrow = mat*DM + col0;

    float o[8][4];
    #pragma unroll
    for (int j=0;j<8;j++){ o[j][0]=0.f;o[j][1]=0.f;o[j][2]=0.f;o[j][3]=0.f; }

    gemm_mma_core<false>(sb, (const char*)g_xh, nullptr, row0, wrow, o);

    const int r = row0 + (wid<<4) + (lane>>2);
    const int b = r>>11, l = r&2047;
    const int bh = b*NH + h;

    if (mat < 2) {
        uint32_t* dh = (uint32_t*)((mat==0)?g_Qh:g_Kh);
        #pragma unroll
        for (int j=0;j<8;j++){
            int dcol = 8*j + ((lane&3)<<1);
            float2 bb = *(const float2*)&bias[col0 + dcol];
            size_t p0 = (((size_t)bh*LSEQ + l)*HDIM + dcol)>>1;
            size_t p1 = (((size_t)bh*LSEQ + l+8)*HDIM + dcol)>>1;
            dh[p0] = hpack(o[j][0]+bb.x, o[j][1]+bb.y);
            dh[p1] = hpack(o[j][2]+bb.x, o[j][3]+bb.y);
        }
    } else {
        float* dv = g_V + ((size_t)bh*LSEQ)*HDIM;
        #pragma unroll
        for (int j=0;j<8;j++){
            int dcol = 8*j + ((lane&3)<<1);
            float2 bb = *(const float2*)&bias[col0 + dcol];
            *(float2*)&dv[(size_t)l*HDIM + dcol]     = make_float2(o[j][0]+bb.x, o[j][1]+bb.y);
            *(float2*)&dv[(size_t)(l+8)*HDIM + dcol] = make_float2(o[j][2]+bb.x, o[j][3]+bb.y);
        }
    }
}

// Output projection: CTX(split fp16, exact A) @ Wo + bo -> d_out fp32
__global__ __launch_bounds__(256,2)
void gemm_out(const float* __restrict__ bo, float* __restrict__ C)
{
    extern __shared__ __align__(128) char smem[];
    const uint32_t sb = (uint32_t)__cvta_generic_to_shared(smem);
    const int tid = threadIdx.x, lane = tid&31, wid = tid>>5;
    const int row0 = blockIdx.x<<7;
    const int col0 = blockIdx.y<<6;
    const int wrow = 3*DM + col0;

    float o[8][4];
    #pragma unroll
    for (int j=0;j<8;j++){ o[j][0]=0.f;o[j][1]=0.f;o[j][2]=0.f;o[j][3]=0.f; }

    gemm_mma_core<true>(sb, (const char*)g_CXh, (const char*)g_CXl, row0, wrow, o);

    const int r = row0 + (wid<<4) + (lane>>2);
    #pragma unroll
    for (int j=0;j<8;j++){
        int dcol = 8*j + ((lane&3)<<1);
        float2 bb = *(const float2*)&bo[col0 + dcol];
        *(float2*)&C[(size_t)r*DOUT + col0 + dcol]     = make_float2(o[j][0]+bb.x, o[j][1]+bb.y);
        *(float2*)&C[(size_t)(r+8)*DOUT + col0 + dcol] = make_float2(o[j][2]+bb.x, o[j][3]+bb.y);
    }
}

// V transpose + convert: g_V [bh][l][d] fp32 -> g_Vth [bh][d][l] fp16
__global__ __launch_bounds__(256)
void vsplit_t()
{
    __shared__ float ts[64][65];
    const int tid = threadIdx.x;
    const int l0 = blockIdx.x<<6;
    const int bh = blockIdx.y;
    const float* src = g_V + ((size_t)bh*LSEQ + l0)*HDIM;
    #pragma unroll
    for (int i=0;i<16;i++){
        int e = tid + (i<<8);
        int r = e>>6, c = e&63;
        ts[c][r] = src[(size_t)r*HDIM + c];
    }
    __syncthreads();
    uint32_t* dh = (uint32_t*)g_Vth;
    #pragma unroll
    for (int i=0;i<8;i++){
        int f = tid + (i<<8);
        int d = f>>5, kp = f&31;
        size_t o = ((size_t)bh*HDIM + d)*(LSEQ/2) + (l0>>1) + kp;
        dh[o] = hpack(ts[d][kp*2], ts[d][kp*2+1]);
    }
}

// ===========================================================================
// Warp-MMA flash attention: S = Q(single) x K(single), O += (Ph+Pl) x V(single).
// SMEM: QH 0 (16K) | KV buf0 @16K (KH 8K, VH 8K) | buf1 @32K = 48K total.
// ===========================================================================
#define SQH 0
#define KVB 16384
#define KH_O 0
#define VH_O 8192
#define ATTN_SMEM 49152

__device__ __forceinline__ void attn_stage_kv(
    uint32_t sb, uint32_t buf, size_t bhb, int k0,
    const char* gkh, const char* gvh)
{
    const int tid = threadIdx.x;
    #pragma unroll
    for (int i=0;i<4;i++){
        int idx = tid + (i<<8);
        int arr = idx>>9, c = idx&511, row = c>>3, j = c&7;
        const char* s; uint32_t off;
        if (arr==0){ s = gkh + bhb + (size_t)(k0+row)*128 + j*16; off = KH_O; }
        else       { s = gvh + bhb + (size_t)row*4096 + k0*2 + j*16; off = VH_O; }
        cpa16(sb + buf + off + swz(row*128 + j*16), s);
    }
}

__global__ __launch_bounds__(256,2)
void attn_mma()
{
    extern __shared__ __align__(128) char smem[];
    const uint32_t sb = (uint32_t)__cvta_generic_to_shared(smem);
    const int tid = threadIdx.x, lane = tid&31, wid = tid>>5;
    const int q0 = blockIdx.x<<7;
    const int bh = blockIdx.y;

    const char* gqh = (const char*)g_Qh;
    const char* gkh = (const char*)g_Kh;
    const char* gvh = (const char*)g_Vth;
    const size_t bhb = (size_t)bh*LSEQ*HDIM*2;

    // stage Q (single) + tile0
    #pragma unroll
    for (int i=0;i<4;i++){
        int idx = tid + (i<<8);
        int row = idx>>3, j = idx&7;
        const char* s = gqh + bhb + (size_t)(q0+row)*128 + j*16;
        cpa16(sb + SQH + swz(row*128 + j*16), s);
    }
    attn_stage_kv(sb, KVB, bhb, 0, gkh, gvh);
    CPCOMMIT();
    cpwait<0>();
    __syncthreads();

    const int qr0 = wid<<4;
    const uint32_t lrow = (uint32_t)(lane&15)*128 + (uint32_t)(lane&16);
    uint32_t qh[4][4];
    #pragma unroll
    for (int c=0;c<4;c++)
        ldsm4(qh[c][0],qh[c][1],qh[c][2],qh[c][3],
              sb + SQH + swz((uint32_t)qr0*128 + lrow + c*32));

    float o[8][4];
    #pragma unroll
    for (int j=0;j<8;j++){ o[j][0]=0.f;o[j][1]=0.f;o[j][2]=0.f;o[j][3]=0.f; }
    float lsum0 = 0.f, lsum1 = 0.f;

    #pragma unroll 1
    for (int kt = 0; kt < LSEQ/64; kt++) {
        const uint32_t buf = KVB + ((uint32_t)(kt&1)<<14);
        if (kt < LSEQ/64 - 1) {
            attn_stage_kv(sb, KVB + ((uint32_t)((kt+1)&1)<<14), bhb, (kt+1)<<6, gkh, gvh);
            CPCOMMIT();
        }
        if (kt > 0) {
            if (kt < LSEQ/64 - 1) cpwait<1>(); else cpwait<0>();
            __syncthreads();
        }

        // ---- S = Q x K (both single fp16) ----
        float s[8][4];
        #pragma unroll
        for (int j=0;j<8;j++){ s[j][0]=0.f;s[j][1]=0.f;s[j][2]=0.f;s[j][3]=0.f; }
        #pragma unroll
        for (int c=0;c<4;c++){
            #pragma unroll
            for (int p=0;p<4;p++){
                uint32_t kh0,kh1,kh2,kh3;
                uint32_t boff = swz((uint32_t)(p<<11) + lrow + c*32);
                ldsm4(kh0,kh1,kh2,kh3, sb + buf + KH_O + boff);
                mma_f16(s[2*p],   qh[c], kh0, kh2);
                mma_f16(s[2*p+1], qh[c], kh1, kh3);
            }
        }

        // ---- epilogue: exp2(scale*s), rowsum, split P into fp16 A-frags ----
        uint32_t ph[4][4], pl[4][4];
        #pragma unroll
        for (int j=0;j<8;j++){
            float p0 = ex2f(s[j][0]*SCALE), p1 = ex2f(s[j][1]*SCALE);
            float p2 = ex2f(s[j][2]*SCALE), p3 = ex2f(s[j][3]*SCALE);
            lsum0 += p0 + p1;  lsum1 += p2 + p3;
            int c = j>>1, r = (j&1)<<1;
            psplit2(p0, p1, ph[c][r+0], pl[c][r+0]);
            psplit2(p2, p3, ph[c][r+1], pl[c][r+1]);
        }

        // ---- O += Ph*Vh + Pl*Vh ----
        #pragma unroll
        for (int c=0;c<4;c++){
            #pragma unroll
            for (int p=0;p<4;p++){
                uint32_t vh0,vh1,vh2,vh3;
                uint32_t boff = swz((uint32_t)(p<<11) + lrow + c*32);
                ldsm4(vh0,vh1,vh2,vh3, sb + buf + VH_O + boff);
                mma_f16(o[2*p],   ph[c], vh0, vh2);
                mma_f16(o[2*p+1], ph[c], vh1, vh3);
                mma_f16(o[2*p],   pl[c], vh0, vh2);
                mma_f16(o[2*p+1], pl[c], vh1, vh3);
            }
        }
        __syncthreads();
    }

    lsum0 += __shfl_xor_sync(0xffffffffu, lsum0, 1);
    lsum0 += __shfl_xor_sync(0xffffffffu, lsum0, 2);
    lsum1 += __shfl_xor_sync(0xffffffffu, lsum1, 1);
    lsum1 += __shfl_xor_sync(0xffffffffu, lsum1, 2);
    const float inv0 = 1.0f/lsum0, inv1 = 1.0f/lsum1;

    const int b = bh>>2, h = bh&3;
    const int r0 = q0 + qr0 + (lane>>2);
    uint32_t* ch = (uint32_t*)g_CXh;
    uint32_t* cl = (uint32_t*)g_CXl;
    #pragma unroll
    for (int j=0;j<8;j++){
        int dcol = 8*j + ((lane&3)<<1);
        float v0 = o[j][0]*inv0, v1 = o[j][1]*inv0;
        float v2 = o[j][2]*inv1, v3 = o[j][3]*inv1;
        uint32_t h0,l0,h1,l1,h2,l2,h3,l3;
        hsplit(v0,h0,l0); hsplit(v1,h1,l1);
        hsplit(v2,h2,l2); hsplit(v3,h3,l3);
        size_t p0 = (((size_t)(b*LSEQ + r0))*DM + h*HDIM + dcol)>>1;
        size_t p1 = (((size_t)(b*LSEQ + r0+8))*DM + h*HDIM + dcol)>>1;
        ch[p0] = h0|(h1<<16);  cl[p0] = l0|(l1<<16);
        ch[p1] = h2|(h3<<16);  cl[p1] = l2|(l3<<16);
    }
}

// ---------------------------------------------------------------------------
extern "C" void kernel_launch(void* const* d_in, const int* in_sizes, int n_in,
                              void* d_out, int out_size)
{
    const float* x  = (const float*)d_in[0];
    const float* Wq = (const float*)d_in[1];
    const float* bq = (const float*)d_in[2];
    const float* Wk = (const float*)d_in[3];
    const float* bk = (const float*)d_in[4];
    const float* Wv = (const float*)d_in[5];
    const float* bv = (const float*)d_in[6];
    const float* Wo = (const float*)d_in[7];
    const float* bo = (const float*)d_in[8];
    float* out = (float*)d_out;

    xcvt<<<2048, 256>>>(x);
    wsplit<<<112, 256>>>(Wq, Wk, Wv, Wo);

    cudaFuncSetAttribute(gemm_qkv, cudaFuncAttributeMaxDynamicSharedMemorySize, GEMM_SMEM_1);
    gemm_qkv<<<dim3(NTOK/128, 12), 256, GEMM_SMEM_1>>>(bq, bk, bv);
    vsplit_t<<<dim3(LSEQ/64, NBH), 256>>>();

    cudaFuncSetAttribute(attn_mma, cudaFuncAttributeMaxDynamicSharedMemorySize, ATTN_SMEM);
    attn_mma<<<dim3(LSEQ/128, NBH), 256, ATTN_SMEM>>>();

    cudaFuncSetAttribute(gemm_out, cudaFuncAttributeMaxDynamicSharedMemorySize, GEMM_SMEM_S);
    gemm_out<<<dim3(NTOK/128, DOUT/64), 256, GEMM_SMEM_S>>>(bo, out);
}

// round 11
// speedup vs baseline: 6.9771x; 1.3955x over previous
#include <cuda_runtime.h>
#include <cuda_fp16.h>
#include <stdint.h>

typedef unsigned long long u64;

#define LSEQ 2048
#define BATCH 8
#define NH 4
#define NBH (BATCH*NH)      // 32
#define HDIM 64
#define DM 256
#define DOUT 1024
#define NTOK (BATCH*LSEQ)   // 16384
#define SCALE 0.090168440055560214f   // log2(e)/16

// ---------------- device scratch (no runtime alloc allowed) ----------------
__device__ __align__(16) unsigned short g_Qh[(size_t)NBH*LSEQ*HDIM];  // fp16 Q (unscaled)
__device__ __align__(16) unsigned short g_Kh[(size_t)NBH*LSEQ*HDIM];  // fp16 K
__device__ __align__(16) unsigned short g_Vth[(size_t)NBH*HDIM*LSEQ]; // fp16 [bh][d][l]
__device__ __align__(16) unsigned short g_xh[(size_t)NTOK*DM];        // fp16 x
__device__ __align__(16) unsigned short g_CXh[(size_t)NTOK*DM];       // fp16 ctx [b,l,h*64+j]
#define WROWS (3*DM + DOUT)   // 1792 rows of W^T (qkv then out)
__device__ __align__(16) unsigned short g_Wh[(size_t)WROWS*DM];       // fp16 W^T [n][k]

// ---------------- scalar helpers ----------------
__device__ __forceinline__ uint32_t hpack(float a, float b){
    __half2 h2 = __floats2half2_rn(a, b);
    return *(uint32_t*)&h2;
}
__device__ __forceinline__ float ex2f(float x){
    float r; asm("ex2.approx.f32 %0,%1;":"=f"(r):"f"(x)); return r; }

// ---------------- warp-MMA + cp.async primitives ----------------
__device__ __forceinline__ void ldsm4(uint32_t &r0, uint32_t &r1, uint32_t &r2, uint32_t &r3, uint32_t addr){
    asm volatile("ldmatrix.sync.aligned.m8n8.x4.shared.b16 {%0,%1,%2,%3},[%4];"
        : "=r"(r0),"=r"(r1),"=r"(r2),"=r"(r3) : "r"(addr));
}
__device__ __forceinline__ void mma_f16(float* d, const uint32_t* a, uint32_t b0, uint32_t b1){
    asm volatile("mma.sync.aligned.m16n8k16.row.col.f32.f16.f16.f32 "
        "{%0,%1,%2,%3},{%4,%5,%6,%7},{%8,%9},{%0,%1,%2,%3};"
        : "+f"(d[0]),"+f"(d[1]),"+f"(d[2]),"+f"(d[3])
        : "r"(a[0]),"r"(a[1]),"r"(a[2]),"r"(a[3]),"r"(b0),"r"(b1));
}
__device__ __forceinline__ uint32_t swz(uint32_t o){ return o ^ ((o>>3)&0x70u); }
__device__ __forceinline__ void cpa16(uint32_t saddr, const void* g){
    asm volatile("cp.async.cg.shared.global [%0],[%1],16;"::"r"(saddr),"l"(g));
}
#define CPCOMMIT() asm volatile("cp.async.commit_group;":::"memory")
template<int N> __device__ __forceinline__ void cpwait(){
    asm volatile("cp.async.wait_group %0;"::"n"(N):"memory");
}

// ===========================================================================
// Prep kernels
// ===========================================================================
__global__ __launch_bounds__(256)
void xcvt(const float* __restrict__ x)
{
    uint32_t* xh = (uint32_t*)g_xh;
    size_t p0 = (size_t)blockIdx.x*1024 + threadIdx.x;
    #pragma unroll
    for (int i=0;i<4;i++){
        size_t p = p0 + (size_t)i*256;
        float2 v = ((const float2*)x)[p];
        xh[p] = hpack(v.x, v.y);
    }
}

// W^T convert (fp16). qkv (3 x 256x256) then Wo (256x1024) -> [n][k].
__global__ __launch_bounds__(256)
void wsplit(const float* __restrict__ Wq, const float* __restrict__ Wk,
            const float* __restrict__ Wv, const float* __restrict__ Wo)
{
    __shared__ float ts[64][65];
    const int tid = threadIdx.x;
    int bx = blockIdx.x;
    const float* W; int N, kt0, nt0, rowbase;
    if (bx < 48) {
        int mat = bx/16, t = bx%16;
        W = (mat==0)?Wq:(mat==1)?Wk:Wv; N = DM;
        kt0 = (t>>2)<<6; nt0 = (t&3)<<6; rowbase = mat*DM + nt0;
    } else {
        bx -= 48;
        W = Wo; N = DOUT;
        kt0 = (bx&3)<<6; nt0 = (bx>>2)<<6; rowbase = 3*DM + nt0;
    }
    #pragma unroll
    for (int i=0;i<16;i++){
        int e = tid + (i<<8);
        int k = e>>6, n = e&63;
        ts[n][k] = W[(size_t)(kt0+k)*N + nt0 + n];
    }
    __syncthreads();
    uint32_t* wh = (uint32_t*)g_Wh;
    #pragma unroll
    for (int i=0;i<8;i++){
        int e = tid + (i<<8);
        int n = e>>5, kp = e&31;
        size_t o = (size_t)(rowbase+n)*(DM/2) + (kt0>>1) + kp;
        wh[o] = hpack(ts[n][kp*2], ts[n][kp*2+1]);
    }
}

// ===========================================================================
// HMMA GEMM core (single-term): 128x64 tile, K=256 in 4 chunks.
// Buffer (24K): AH 16K + WH 8K. Double-buffered = 48K.
// ===========================================================================
#define GAH 0
#define GWH 16384
#define GBUF 24576
#define GEMM_SMEM 49152

__device__ __forceinline__ void gemm_stage(
    uint32_t sb, uint32_t buf, const char* gah, int row0, int wrow, int kt)
{
    const int tid = threadIdx.x;
    const char* gwh = (const char*)g_Wh;
    #pragma unroll
    for (int i=0;i<4;i++){
        int idx = tid + (i<<8);
        int row = idx>>3, j = idx&7;
        const char* s = gah + (size_t)(row0+row)*512 + kt*128 + j*16;
        cpa16(sb + buf + GAH + swz(row*128 + j*16), s);
    }
    #pragma unroll
    for (int i=0;i<2;i++){
        int idx = tid + (i<<8);
        int row = idx>>3, j = idx&7;
        const char* s = gwh + (size_t)(wrow+row)*512 + kt*128 + j*16;
        cpa16(sb + buf + GWH + swz(row*128 + j*16), s);
    }
}

__device__ __forceinline__ void gemm_mma_core(
    uint32_t sb, const char* gah, int row0, int wrow, float (&o)[8][4])
{
    const int tid = threadIdx.x, lane = tid&31, wid = tid>>5;
    const uint32_t lrow = (uint32_t)(lane&15)*128 + (uint32_t)(lane&16);

    gemm_stage(sb, 0, gah, row0, wrow, 0);
    CPCOMMIT();

    #pragma unroll 1
    for (int kt = 0; kt < 4; kt++) {
        const uint32_t buf = (kt&1) ? GBUF : 0;
        if (kt < 3) {
            gemm_stage(sb, (kt&1)?0:GBUF, gah, row0, wrow, kt+1);
            CPCOMMIT();
            cpwait<1>();
        } else {
            cpwait<0>();
        }
        __syncthreads();

        const uint32_t abase = sb + buf + (uint32_t)(wid<<4)*128;
        #pragma unroll
        for (int c=0;c<4;c++){
            uint32_t ah[4];
            ldsm4(ah[0],ah[1],ah[2],ah[3], abase + GAH + swz(lrow + c*32));
            #pragma unroll
            for (int p=0;p<4;p++){
                uint32_t wh0,wh1,wh2,wh3;
                uint32_t boff = swz((uint32_t)(p<<11) + lrow + c*32);
                ldsm4(wh0,wh1,wh2,wh3, sb + buf + GWH + boff);
                mma_f16(o[2*p],   ah, wh0, wh2);
                mma_f16(o[2*p+1], ah, wh1, wh3);
            }
        }
        __syncthreads();
    }
}

// QKV projection: Q/K -> fp16 [bh][l][d]; V -> fp16 transposed [bh][d][l] (fused)
__global__ __launch_bounds__(256,2)
void gemm_qkv(const float* __restrict__ bq, const float* __restrict__ bk,
              const float* __restrict__ bv)
{
    extern __shared__ __align__(128) char smem[];
    const uint32_t sb = (uint32_t)__cvta_generic_to_shared(smem);
    const int tid = threadIdx.x, lane = tid&31, wid = tid>>5;
    const int row0 = blockIdx.x<<7;
    const int yy = blockIdx.y, mat = yy>>2, h = yy&3;
    const int col0 = h<<6;
    const float* bias = (mat==0)?bq:(mat==1)?bk:bv;
    const int wrow = mat*DM + col0;

    float o[8][4];
    #pragma unroll
    for (int j=0;j<8;j++){ o[j][0]=0.f;o[j][1]=0.f;o[j][2]=0.f;o[j][3]=0.f; }

    gemm_mma_core(sb, (const char*)g_xh, row0, wrow, o);

    const int r = row0 + (wid<<4) + (lane>>2);
    const int b = r>>11, l = r&2047;
    const int bh = b*NH + h;

    if (mat < 2) {
        uint32_t* dh = (uint32_t*)((mat==0)?g_Qh:g_Kh);
        #pragma unroll
        for (int j=0;j<8;j++){
            int dcol = 8*j + ((lane&3)<<1);
            float2 bb = *(const float2*)&bias[col0 + dcol];
            size_t p0 = (((size_t)bh*LSEQ + l)*HDIM + dcol)>>1;
            size_t p1 = (((size_t)bh*LSEQ + l+8)*HDIM + dcol)>>1;
            dh[p0] = hpack(o[j][0]+bb.x, o[j][1]+bb.y);
            dh[p1] = hpack(o[j][2]+bb.x, o[j][3]+bb.y);
        }
    } else {
        // fused V transpose: stage fp16 into smem vt[64 d][128 l] then coalesced out
        __half* vt = (__half*)smem;      // 64*128 halves = 16 KB
        const int lloc = (wid<<4) + (lane>>2);
        #pragma unroll
        for (int j=0;j<8;j++){
            int dcol = 8*j + ((lane&3)<<1);
            float2 bb = *(const float2*)&bias[col0 + dcol];
            vt[(dcol+0)*128 + lloc]   = __float2half_rn(o[j][0]+bb.x);
            vt[(dcol+1)*128 + lloc]   = __float2half_rn(o[j][1]+bb.y);
            vt[(dcol+0)*128 + lloc+8] = __float2half_rn(o[j][2]+bb.x);
            vt[(dcol+1)*128 + lloc+8] = __float2half_rn(o[j][3]+bb.y);
        }
        __syncthreads();
        const int l0 = row0 & 2047;
        // row = 128 halves = 256 B = 16 uint4  (FIX: was 8/row in R10)
        #pragma unroll
        for (int i=0;i<4;i++){
            int e = tid + (i<<8);           // 0..1023 uint4s
            int d = e>>4, j16 = e&15;
            uint4 v = ((const uint4*)vt)[e];
            *(uint4*)((char*)g_Vth + (((size_t)(bh*HDIM + d))*LSEQ + l0)*2 + j16*16) = v;
        }
    }
}

// Output projection: CTX(fp16) @ Wo + bo -> d_out fp32
__global__ __launch_bounds__(256,2)
void gemm_out(const float* __restrict__ bo, float* __restrict__ C)
{
    extern __shared__ __align__(128) char smem[];
    const uint32_t sb = (uint32_t)__cvta_generic_to_shared(smem);
    const int tid = threadIdx.x, lane = tid&31, wid = tid>>5;
    const int row0 = blockIdx.x<<7;
    const int col0 = blockIdx.y<<6;
    const int wrow = 3*DM + col0;

    float o[8][4];
    #pragma unroll
    for (int j=0;j<8;j++){ o[j][0]=0.f;o[j][1]=0.f;o[j][2]=0.f;o[j][3]=0.f; }

    gemm_mma_core(sb, (const char*)g_CXh, row0, wrow, o);

    const int r = row0 + (wid<<4) + (lane>>2);
    #pragma unroll
    for (int j=0;j<8;j++){
        int dcol = 8*j + ((lane&3)<<1);
        float2 bb = *(const float2*)&bo[col0 + dcol];
        *(float2*)&C[(size_t)r*DOUT + col0 + dcol]     = make_float2(o[j][0]+bb.x, o[j][1]+bb.y);
        *(float2*)&C[(size_t)(r+8)*DOUT + col0 + dcol] = make_float2(o[j][2]+bb.x, o[j][3]+bb.y);
    }
}

// ===========================================================================
// Warp-MMA flash attention: S = QxK (fp16), O += P(fp16) x V(fp16).
// SMEM: QH 0 (16K) | KV buf0 @16K (KH 8K, VH 8K) | buf1 @32K = 48K total.
// ===========================================================================
#define SQH 0
#define KVB 16384
#define KH_O 0
#define VH_O 8192
#define ATTN_SMEM 49152

__device__ __forceinline__ void attn_stage_kv(
    uint32_t sb, uint32_t buf, size_t bhb, int k0,
    const char* gkh, const char* gvh)
{
    const int tid = threadIdx.x;
    #pragma unroll
    for (int i=0;i<4;i++){
        int idx = tid + (i<<8);
        int arr = idx>>9, c = idx&511, row = c>>3, j = c&7;
        const char* s; uint32_t off;
        if (arr==0){ s = gkh + bhb + (size_t)(k0+row)*128 + j*16; off = KH_O; }
        else       { s = gvh + bhb + (size_t)row*4096 + k0*2 + j*16; off = VH_O; }
        cpa16(sb + buf + off + swz(row*128 + j*16), s);
    }
}

__global__ __launch_bounds__(256,2)
void attn_mma()
{
    extern __shared__ __align__(128) char smem[];
    const uint32_t sb = (uint32_t)__cvta_generic_to_shared(smem);
    const int tid = threadIdx.x, lane = tid&31, wid = tid>>5;
    const int q0 = blockIdx.x<<7;
    const int bh = blockIdx.y;

    const char* gqh = (const char*)g_Qh;
    const char* gkh = (const char*)g_Kh;
    const char* gvh = (const char*)g_Vth;
    const size_t bhb = (size_t)bh*LSEQ*HDIM*2;

    // stage Q + tile0
    #pragma unroll
    for (int i=0;i<4;i++){
        int idx = tid + (i<<8);
        int row = idx>>3, j = idx&7;
        const char* s = gqh + bhb + (size_t)(q0+row)*128 + j*16;
        cpa16(sb + SQH + swz(row*128 + j*16), s);
    }
    attn_stage_kv(sb, KVB, bhb, 0, gkh, gvh);
    CPCOMMIT();
    cpwait<0>();
    __syncthreads();

    const int qr0 = wid<<4;
    const uint32_t lrow = (uint32_t)(lane&15)*128 + (uint32_t)(lane&16);
    uint32_t qh[4][4];
    #pragma unroll
    for (int c=0;c<4;c++)
        ldsm4(qh[c][0],qh[c][1],qh[c][2],qh[c][3],
              sb + SQH + swz((uint32_t)qr0*128 + lrow + c*32));

    float o[8][4];
    #pragma unroll
    for (int j=0;j<8;j++){ o[j][0]=0.f;o[j][1]=0.f;o[j][2]=0.f;o[j][3]=0.f; }
    float lsum0 = 0.f, lsum1 = 0.f;

    #pragma unroll 1
    for (int kt = 0; kt < LSEQ/64; kt++) {
        const uint32_t buf = KVB + ((uint32_t)(kt&1)<<14);
        if (kt < LSEQ/64 - 1) {
            attn_stage_kv(sb, KVB + ((uint32_t)((kt+1)&1)<<14), bhb, (kt+1)<<6, gkh, gvh);
            CPCOMMIT();
        }
        if (kt > 0) {
            if (kt < LSEQ/64 - 1) cpwait<1>(); else cpwait<0>();
            __syncthreads();
        }

        // ---- S = Q x K ----
        float s[8][4];
        #pragma unroll
        for (int j=0;j<8;j++){ s[j][0]=0.f;s[j][1]=0.f;s[j][2]=0.f;s[j][3]=0.f; }
        #pragma unroll
        for (int c=0;c<4;c++){
            #pragma unroll
            for (int p=0;p<4;p++){
                uint32_t kh0,kh1,kh2,kh3;
                uint32_t boff = swz((uint32_t)(p<<11) + lrow + c*32);
                ldsm4(kh0,kh1,kh2,kh3, sb + buf + KH_O + boff);
                mma_f16(s[2*p],   qh[c], kh0, kh2);
                mma_f16(s[2*p+1], qh[c], kh1, kh3);
            }
        }

        // ---- epilogue: exp2(scale*s), rowsum, P -> fp16 A-frags ----
        uint32_t ph[4][4];
        #pragma unroll
        for (int j=0;j<8;j++){
            float p0 = ex2f(s[j][0]*SCALE), p1 = ex2f(s[j][1]*SCALE);
            float p2 = ex2f(s[j][2]*SCALE), p3 = ex2f(s[j][3]*SCALE);
            lsum0 += p0 + p1;  lsum1 += p2 + p3;
            int c = j>>1, r = (j&1)<<1;
            ph[c][r+0] = hpack(p0, p1);
            ph[c][r+1] = hpack(p2, p3);
        }

        // ---- O += P x V ----
        #pragma unroll
        for (int c=0;c<4;c++){
            #pragma unroll
            for (int p=0;p<4;p++){
                uint32_t vh0,vh1,vh2,vh3;
                uint32_t boff = swz((uint32_t)(p<<11) + lrow + c*32);
                ldsm4(vh0,vh1,vh2,vh3, sb + buf + VH_O + boff);
                mma_f16(o[2*p],   ph[c], vh0, vh2);
                mma_f16(o[2*p+1], ph[c], vh1, vh3);
            }
        }
        __syncthreads();
    }

    lsum0 += __shfl_xor_sync(0xffffffffu, lsum0, 1);
    lsum0 += __shfl_xor_sync(0xffffffffu, lsum0, 2);
    lsum1 += __shfl_xor_sync(0xffffffffu, lsum1, 1);
    lsum1 += __shfl_xor_sync(0xffffffffu, lsum1, 2);
    const float inv0 = 1.0f/lsum0, inv1 = 1.0f/lsum1;

    const int b = bh>>2, h = bh&3;
    const int r0 = q0 + qr0 + (lane>>2);
    uint32_t* ch = (uint32_t*)g_CXh;
    #pragma unroll
    for (int j=0;j<8;j++){
        int dcol = 8*j + ((lane&3)<<1);
        size_t p0 = (((size_t)(b*LSEQ + r0))*DM + h*HDIM + dcol)>>1;
        size_t p1 = (((size_t)(b*LSEQ + r0+8))*DM + h*HDIM + dcol)>>1;
        ch[p0] = hpack(o[j][0]*inv0, o[j][1]*inv0);
        ch[p1] = hpack(o[j][2]*inv1, o[j][3]*inv1);
    }
}

// ---------------------------------------------------------------------------
extern "C" void kernel_launch(void* const* d_in, const int* in_sizes, int n_in,
                              void* d_out, int out_size)
{
    const float* x  = (const float*)d_in[0];
    const float* Wq = (const float*)d_in[1];
    const float* bq = (const float*)d_in[2];
    const float* Wk = (const float*)d_in[3];
    const float* bk = (const float*)d_in[4];
    const float* Wv = (const float*)d_in[5];
    const float* bv = (const float*)d_in[6];
    const float* Wo = (const float*)d_in[7];
    const float* bo = (const float*)d_in[8];
    float* out = (float*)d_out;

    xcvt<<<2048, 256>>>(x);
    wsplit<<<112, 256>>>(Wq, Wk, Wv, Wo);

    cudaFuncSetAttribute(gemm_qkv, cudaFuncAttributeMaxDynamicSharedMemorySize, GEMM_SMEM);
    gemm_qkv<<<dim3(NTOK/128, 12), 256, GEMM_SMEM>>>(bq, bk, bv);

    cudaFuncSetAttribute(attn_mma, cudaFuncAttributeMaxDynamicSharedMemorySize, ATTN_SMEM);
    attn_mma<<<dim3(LSEQ/128, NBH), 256, ATTN_SMEM>>>();

    cudaFuncSetAttribute(gemm_out, cudaFuncAttributeMaxDynamicSharedMemorySize, GEMM_SMEM);
    gemm_out<<<dim3(NTOK/128, DOUT/64), 256, GEMM_SMEM>>>(bo, out);
}